// round 3
// baseline (speedup 1.0000x reference)
#include <cuda_runtime.h>

// Problem constants
#define SQ   4096
#define DM   1024
#define NH   16
#define HDIM 64

// Scratch (allocation-free rule: __device__ globals)
__device__ float g_q[SQ * DM];
__device__ float g_k[SQ * DM];
__device__ float g_v[SQ * DM];
__device__ float g_ctx[SQ * DM];

// Compile-time scratch selector (avoids cudaGetSymbolAddress on host)
template <int SEL> __device__ __forceinline__ float* scratch_ptr();
template <> __device__ __forceinline__ float* scratch_ptr<0>() { return g_q; }
template <> __device__ __forceinline__ float* scratch_ptr<1>() { return g_k; }
template <> __device__ __forceinline__ float* scratch_ptr<2>() { return g_v; }
template <> __device__ __forceinline__ float* scratch_ptr<3>() { return g_ctx; }

// ---------------------------------------------------------------------------
// SGEMM core: C[M,N] = A[M,K] * B[N,K]^T (+ bias[n])
// BM=BN=128, BK=16, 256 threads, 8x8 micro-tile (split 4+4 halves).
// Double-buffered smem, register prefetch. M=N=K=1024-multiples assumed.
// ---------------------------------------------------------------------------
template <bool BIAS>
__device__ __forceinline__
void gemm_body(const float* __restrict__ A, const float* __restrict__ B,
               const float* __restrict__ bias, float* __restrict__ C,
               int M, int N, int K)
{
    __shared__ float As[2][16 * 132];
    __shared__ float Bs[2][16 * 132];

    const int tid = threadIdx.x;
    const int tx  = tid & 15;
    const int ty  = tid >> 4;
    const int m0  = blockIdx.y * 128;
    const int n0  = blockIdx.x * 128;

    const int lrow = tid >> 2;         // 0..63
    const int lc4  = (tid & 3) * 4;    // 0,4,8,12

    float acc[8][8];
#pragma unroll
    for (int i = 0; i < 8; i++)
#pragma unroll
        for (int j = 0; j < 8; j++) acc[i][j] = 0.f;

    float4 ra[2], rb[2];
    const int T = K >> 4;

    // Prologue: load tile 0
#pragma unroll
    for (int e = 0; e < 2; e++) {
        int row = lrow + e * 64;
        ra[e] = *(const float4*)(A + (size_t)(m0 + row) * K + lc4);
        rb[e] = *(const float4*)(B + (size_t)(n0 + row) * K + lc4);
    }
#pragma unroll
    for (int e = 0; e < 2; e++) {
        int row = lrow + e * 64;
        As[0][(lc4 + 0) * 132 + row] = ra[e].x;
        As[0][(lc4 + 1) * 132 + row] = ra[e].y;
        As[0][(lc4 + 2) * 132 + row] = ra[e].z;
        As[0][(lc4 + 3) * 132 + row] = ra[e].w;
        Bs[0][(lc4 + 0) * 132 + row] = rb[e].x;
        Bs[0][(lc4 + 1) * 132 + row] = rb[e].y;
        Bs[0][(lc4 + 2) * 132 + row] = rb[e].z;
        Bs[0][(lc4 + 3) * 132 + row] = rb[e].w;
    }
    __syncthreads();

    int buf = 0;
    for (int t = 0; t < T; t++) {
        if (t + 1 < T) {
            int k0 = (t + 1) * 16;
#pragma unroll
            for (int e = 0; e < 2; e++) {
                int row = lrow + e * 64;
                ra[e] = *(const float4*)(A + (size_t)(m0 + row) * K + k0 + lc4);
                rb[e] = *(const float4*)(B + (size_t)(n0 + row) * K + k0 + lc4);
            }
        }
#pragma unroll
        for (int kk = 0; kk < 16; kk++) {
            float4 a0 = *(const float4*)&As[buf][kk * 132 + ty * 4];
            float4 a1 = *(const float4*)&As[buf][kk * 132 + 64 + ty * 4];
            float4 b0 = *(const float4*)&Bs[buf][kk * 132 + tx * 4];
            float4 b1 = *(const float4*)&Bs[buf][kk * 132 + 64 + tx * 4];
            float av[8] = {a0.x, a0.y, a0.z, a0.w, a1.x, a1.y, a1.z, a1.w};
            float bv[8] = {b0.x, b0.y, b0.z, b0.w, b1.x, b1.y, b1.z, b1.w};
#pragma unroll
            for (int i = 0; i < 8; i++)
#pragma unroll
                for (int j = 0; j < 8; j++)
                    acc[i][j] += av[i] * bv[j];
        }
        if (t + 1 < T) {
            int nb = buf ^ 1;
#pragma unroll
            for (int e = 0; e < 2; e++) {
                int row = lrow + e * 64;
                As[nb][(lc4 + 0) * 132 + row] = ra[e].x;
                As[nb][(lc4 + 1) * 132 + row] = ra[e].y;
                As[nb][(lc4 + 2) * 132 + row] = ra[e].z;
                As[nb][(lc4 + 3) * 132 + row] = ra[e].w;
                Bs[nb][(lc4 + 0) * 132 + row] = rb[e].x;
                Bs[nb][(lc4 + 1) * 132 + row] = rb[e].y;
                Bs[nb][(lc4 + 2) * 132 + row] = rb[e].z;
                Bs[nb][(lc4 + 3) * 132 + row] = rb[e].w;
            }
            __syncthreads();
            buf = nb;
        }
    }

    // Epilogue
#pragma unroll
    for (int ih = 0; ih < 2; ih++) {
#pragma unroll
        for (int i = 0; i < 4; i++) {
            int m  = m0 + ih * 64 + ty * 4 + i;
            int iv = ih * 4 + i;
#pragma unroll
            for (int jh = 0; jh < 2; jh++) {
                int n = n0 + jh * 64 + tx * 4;
                int jv = jh * 4;
                float4 r;
                r.x = acc[iv][jv + 0];
                r.y = acc[iv][jv + 1];
                r.z = acc[iv][jv + 2];
                r.w = acc[iv][jv + 3];
                if (BIAS) {
                    r.x += bias[n + 0];
                    r.y += bias[n + 1];
                    r.z += bias[n + 2];
                    r.w += bias[n + 3];
                }
                *(float4*)(C + (size_t)m * N + n) = r;
            }
        }
    }
}

// Projection GEMM: C = scratch<OUTSEL>, inputs from harness pointers
template <int OUTSEL>
__global__ __launch_bounds__(256, 2)
void gemm_proj(const float* __restrict__ A, const float* __restrict__ B)
{
    gemm_body<false>(A, B, nullptr, scratch_ptr<OUTSEL>(), SQ, DM, DM);
}

// Output GEMM: A = g_ctx, C = harness output, with bias
__global__ __launch_bounds__(256, 2)
void gemm_out(const float* __restrict__ B, const float* __restrict__ bias,
              float* __restrict__ C)
{
    gemm_body<true>(g_ctx, B, bias, C, SQ, DM, DM);
}

// ---------------------------------------------------------------------------
// Flash attention, causal. One CTA per (query-block of 64, head).
// Br=Bc=64, 256 threads (16x16), 4x4 micro-tiles, online softmax.
// Smem: Qs [64][68], KV union (K^T then V) [64][68], Ps [64][68]  -> 52224 B
// ---------------------------------------------------------------------------
__global__ __launch_bounds__(256)
void attn_kernel()
{
    extern __shared__ float sm[];
    float* Qs = sm;                  // [r][d] stride 68
    float* KV = sm + 64 * 68;        // K^T [d][r] / V [r][d], stride 68
    float* Ps = sm + 2 * 64 * 68;    // [r][c] stride 68

    const float* q = g_q;
    const float* k = g_k;
    const float* v = g_v;
    float* ctx = g_ctx;

    const int qb  = blockIdx.x;
    const int h   = blockIdx.y;
    const int tid = threadIdx.x;
    const int tx  = tid & 15;
    const int ty  = tid >> 4;
    const int hoff = h * HDIM;

    const int lr = tid >> 2;          // 0..63
    const int lc = (tid & 3) * 16;    // 0,16,32,48

    // Load Q tile [64 x 64]
#pragma unroll
    for (int f = 0; f < 4; f++) {
        float4 t4 = *(const float4*)(q + (size_t)(qb * 64 + lr) * DM + hoff + lc + f * 4);
        *(float4*)&Qs[lr * 68 + lc + f * 4] = t4;
    }

    float acc[4][4];
#pragma unroll
    for (int i = 0; i < 4; i++)
#pragma unroll
        for (int j = 0; j < 4; j++) acc[i][j] = 0.f;
    float mi[4], li[4];
#pragma unroll
    for (int i = 0; i < 4; i++) { mi[i] = -1e30f; li[i] = 0.f; }

    for (int kb = 0; kb <= qb; kb++) {
        __syncthreads();   // previous PV reads done before overwriting KV; Q visible

        // Load K tile transposed: KV[d][r]
#pragma unroll
        for (int f = 0; f < 4; f++) {
            float4 t4 = *(const float4*)(k + (size_t)(kb * 64 + lr) * DM + hoff + lc + f * 4);
            int c = lc + f * 4;
            KV[(c + 0) * 68 + lr] = t4.x;
            KV[(c + 1) * 68 + lr] = t4.y;
            KV[(c + 2) * 68 + lr] = t4.z;
            KV[(c + 3) * 68 + lr] = t4.w;
        }
        __syncthreads();

        // S = Q K^T (64x64), 4x4 per thread
        float s[4][4];
#pragma unroll
        for (int i = 0; i < 4; i++)
#pragma unroll
            for (int j = 0; j < 4; j++) s[i][j] = 0.f;
#pragma unroll 4
        for (int d = 0; d < 64; d++) {
            float a0 = Qs[(ty * 4 + 0) * 68 + d];
            float a1 = Qs[(ty * 4 + 1) * 68 + d];
            float a2 = Qs[(ty * 4 + 2) * 68 + d];
            float a3 = Qs[(ty * 4 + 3) * 68 + d];
            float4 b = *(const float4*)&KV[d * 68 + tx * 4];
            s[0][0] += a0 * b.x; s[0][1] += a0 * b.y; s[0][2] += a0 * b.z; s[0][3] += a0 * b.w;
            s[1][0] += a1 * b.x; s[1][1] += a1 * b.y; s[1][2] += a1 * b.z; s[1][3] += a1 * b.w;
            s[2][0] += a2 * b.x; s[2][1] += a2 * b.y; s[2][2] += a2 * b.z; s[2][3] += a2 * b.w;
            s[3][0] += a3 * b.x; s[3][1] += a3 * b.y; s[3][2] += a3 * b.z; s[3][3] += a3 * b.w;
        }

        const float scale = 0.125f;   // 1/sqrt(64)
#pragma unroll
        for (int i = 0; i < 4; i++) {
            int qi = qb * 64 + ty * 4 + i;
            float rm = -1e30f;
#pragma unroll
            for (int j = 0; j < 4; j++) {
                int kj = kb * 64 + tx * 4 + j;
                s[i][j] = (kj <= qi) ? s[i][j] * scale : -1e30f;
                rm = fmaxf(rm, s[i][j]);
            }
#pragma unroll
            for (int off = 8; off; off >>= 1)
                rm = fmaxf(rm, __shfl_xor_sync(0xffffffffu, rm, off));
            float mnew = fmaxf(mi[i], rm);
            float rs = 0.f;
#pragma unroll
            for (int j = 0; j < 4; j++) {
                s[i][j] = __expf(s[i][j] - mnew);
                rs += s[i][j];
            }
#pragma unroll
            for (int off = 8; off; off >>= 1)
                rs += __shfl_xor_sync(0xffffffffu, rs, off);
            float corr = __expf(mi[i] - mnew);
            li[i] = li[i] * corr + rs;
#pragma unroll
            for (int j = 0; j < 4; j++) acc[i][j] *= corr;
            mi[i] = mnew;
            float4 p4; p4.x = s[i][0]; p4.y = s[i][1]; p4.z = s[i][2]; p4.w = s[i][3];
            *(float4*)&Ps[(ty * 4 + i) * 68 + tx * 4] = p4;
        }
        __syncthreads();  // P fully written, K reads done

        // Load V tile (natural layout) into KV
#pragma unroll
        for (int f = 0; f < 4; f++) {
            float4 t4 = *(const float4*)(v + (size_t)(kb * 64 + lr) * DM + hoff + lc + f * 4);
            *(float4*)&KV[lr * 68 + lc + f * 4] = t4;
        }
        __syncthreads();

        // O += P V
#pragma unroll 4
        for (int kk = 0; kk < 64; kk++) {
            float p0 = Ps[(ty * 4 + 0) * 68 + kk];
            float p1 = Ps[(ty * 4 + 1) * 68 + kk];
            float p2 = Ps[(ty * 4 + 2) * 68 + kk];
            float p3 = Ps[(ty * 4 + 3) * 68 + kk];
            float4 vv = *(const float4*)&KV[kk * 68 + tx * 4];
            acc[0][0] += p0 * vv.x; acc[0][1] += p0 * vv.y; acc[0][2] += p0 * vv.z; acc[0][3] += p0 * vv.w;
            acc[1][0] += p1 * vv.x; acc[1][1] += p1 * vv.y; acc[1][2] += p1 * vv.z; acc[1][3] += p1 * vv.w;
            acc[2][0] += p2 * vv.x; acc[2][1] += p2 * vv.y; acc[2][2] += p2 * vv.z; acc[2][3] += p2 * vv.w;
            acc[3][0] += p3 * vv.x; acc[3][1] += p3 * vv.y; acc[3][2] += p3 * vv.z; acc[3][3] += p3 * vv.w;
        }
    }

    // Finalize: ctx[s][h*64 + d] = O / l
#pragma unroll
    for (int i = 0; i < 4; i++) {
        float inv = 1.0f / li[i];
        float4 o;
        o.x = acc[i][0] * inv;
        o.y = acc[i][1] * inv;
        o.z = acc[i][2] * inv;
        o.w = acc[i][3] * inv;
        *(float4*)(ctx + (size_t)(qb * 64 + ty * 4 + i) * DM + hoff + tx * 4) = o;
    }
}

// ---------------------------------------------------------------------------
extern "C" void kernel_launch(void* const* d_in, const int* in_sizes, int n_in,
                              void* d_out, int out_size)
{
    const float* x  = (const float*)d_in[0];
    const float* Wq = (const float*)d_in[1];
    const float* Wk = (const float*)d_in[2];
    const float* Wv = (const float*)d_in[3];
    const float* Wo = (const float*)d_in[4];
    const float* bo = (const float*)d_in[5];
    float* out = (float*)d_out;

    dim3 gg(DM / 128, SQ / 128);   // (8, 32)
    gemm_proj<0><<<gg, 256>>>(x, Wq);
    gemm_proj<1><<<gg, 256>>>(x, Wk);
    gemm_proj<2><<<gg, 256>>>(x, Wv);

    const int smem_attn = 3 * 64 * 68 * sizeof(float);   // 52224 B
    cudaFuncSetAttribute(attn_kernel, cudaFuncAttributeMaxDynamicSharedMemorySize, smem_attn);
    attn_kernel<<<dim3(SQ / 64, NH), 256, smem_attn>>>();

    gemm_out<<<gg, 256>>>(Wo, bo, out);
}

// round 4
// speedup vs baseline: 1.0485x; 1.0485x over previous
#include <cuda_runtime.h>

// Problem constants
#define SQ   4096
#define DM   1024
#define NH   16
#define HDIM 64

// Scratch (allocation-free rule: __device__ globals)
__device__ float g_q[SQ * DM];
__device__ float g_k[SQ * DM];
__device__ float g_v[SQ * DM];
__device__ float g_ctx[SQ * DM];

// Compile-time scratch selector (avoids cudaGetSymbolAddress on host)
template <int SEL> __device__ __forceinline__ float* scratch_ptr();
template <> __device__ __forceinline__ float* scratch_ptr<0>() { return g_q; }
template <> __device__ __forceinline__ float* scratch_ptr<1>() { return g_k; }
template <> __device__ __forceinline__ float* scratch_ptr<2>() { return g_v; }
template <> __device__ __forceinline__ float* scratch_ptr<3>() { return g_ctx; }

// ---------------------------------------------------------------------------
// SGEMM core: C[M,N] = A[M,K] * B[N,K]^T (+ bias[n])   (unchanged, passing)
// ---------------------------------------------------------------------------
template <bool BIAS>
__device__ __forceinline__
void gemm_body(const float* __restrict__ A, const float* __restrict__ B,
               const float* __restrict__ bias, float* __restrict__ C,
               int M, int N, int K)
{
    __shared__ float As[2][16 * 132];
    __shared__ float Bs[2][16 * 132];

    const int tid = threadIdx.x;
    const int tx  = tid & 15;
    const int ty  = tid >> 4;
    const int m0  = blockIdx.y * 128;
    const int n0  = blockIdx.x * 128;

    const int lrow = tid >> 2;
    const int lc4  = (tid & 3) * 4;

    float acc[8][8];
#pragma unroll
    for (int i = 0; i < 8; i++)
#pragma unroll
        for (int j = 0; j < 8; j++) acc[i][j] = 0.f;

    float4 ra[2], rb[2];
    const int T = K >> 4;

#pragma unroll
    for (int e = 0; e < 2; e++) {
        int row = lrow + e * 64;
        ra[e] = *(const float4*)(A + (size_t)(m0 + row) * K + lc4);
        rb[e] = *(const float4*)(B + (size_t)(n0 + row) * K + lc4);
    }
#pragma unroll
    for (int e = 0; e < 2; e++) {
        int row = lrow + e * 64;
        As[0][(lc4 + 0) * 132 + row] = ra[e].x;
        As[0][(lc4 + 1) * 132 + row] = ra[e].y;
        As[0][(lc4 + 2) * 132 + row] = ra[e].z;
        As[0][(lc4 + 3) * 132 + row] = ra[e].w;
        Bs[0][(lc4 + 0) * 132 + row] = rb[e].x;
        Bs[0][(lc4 + 1) * 132 + row] = rb[e].y;
        Bs[0][(lc4 + 2) * 132 + row] = rb[e].z;
        Bs[0][(lc4 + 3) * 132 + row] = rb[e].w;
    }
    __syncthreads();

    int buf = 0;
    for (int t = 0; t < T; t++) {
        if (t + 1 < T) {
            int k0 = (t + 1) * 16;
#pragma unroll
            for (int e = 0; e < 2; e++) {
                int row = lrow + e * 64;
                ra[e] = *(const float4*)(A + (size_t)(m0 + row) * K + k0 + lc4);
                rb[e] = *(const float4*)(B + (size_t)(n0 + row) * K + k0 + lc4);
            }
        }
#pragma unroll
        for (int kk = 0; kk < 16; kk++) {
            float4 a0 = *(const float4*)&As[buf][kk * 132 + ty * 4];
            float4 a1 = *(const float4*)&As[buf][kk * 132 + 64 + ty * 4];
            float4 b0 = *(const float4*)&Bs[buf][kk * 132 + tx * 4];
            float4 b1 = *(const float4*)&Bs[buf][kk * 132 + 64 + tx * 4];
            float av[8] = {a0.x, a0.y, a0.z, a0.w, a1.x, a1.y, a1.z, a1.w};
            float bv[8] = {b0.x, b0.y, b0.z, b0.w, b1.x, b1.y, b1.z, b1.w};
#pragma unroll
            for (int i = 0; i < 8; i++)
#pragma unroll
                for (int j = 0; j < 8; j++)
                    acc[i][j] += av[i] * bv[j];
        }
        if (t + 1 < T) {
            int nb = buf ^ 1;
#pragma unroll
            for (int e = 0; e < 2; e++) {
                int row = lrow + e * 64;
                As[nb][(lc4 + 0) * 132 + row] = ra[e].x;
                As[nb][(lc4 + 1) * 132 + row] = ra[e].y;
                As[nb][(lc4 + 2) * 132 + row] = ra[e].z;
                As[nb][(lc4 + 3) * 132 + row] = ra[e].w;
                Bs[nb][(lc4 + 0) * 132 + row] = rb[e].x;
                Bs[nb][(lc4 + 1) * 132 + row] = rb[e].y;
                Bs[nb][(lc4 + 2) * 132 + row] = rb[e].z;
                Bs[nb][(lc4 + 3) * 132 + row] = rb[e].w;
            }
            __syncthreads();
            buf = nb;
        }
    }

#pragma unroll
    for (int ih = 0; ih < 2; ih++) {
#pragma unroll
        for (int i = 0; i < 4; i++) {
            int m  = m0 + ih * 64 + ty * 4 + i;
            int iv = ih * 4 + i;
#pragma unroll
            for (int jh = 0; jh < 2; jh++) {
                int n = n0 + jh * 64 + tx * 4;
                int jv = jh * 4;
                float4 r;
                r.x = acc[iv][jv + 0];
                r.y = acc[iv][jv + 1];
                r.z = acc[iv][jv + 2];
                r.w = acc[iv][jv + 3];
                if (BIAS) {
                    r.x += bias[n + 0];
                    r.y += bias[n + 1];
                    r.z += bias[n + 2];
                    r.w += bias[n + 3];
                }
                *(float4*)(C + (size_t)m * N + n) = r;
            }
        }
    }
}

template <int OUTSEL>
__global__ __launch_bounds__(256, 2)
void gemm_proj(const float* __restrict__ A, const float* __restrict__ B)
{
    gemm_body<false>(A, B, nullptr, scratch_ptr<OUTSEL>(), SQ, DM, DM);
}

__global__ __launch_bounds__(256, 2)
void gemm_out(const float* __restrict__ B, const float* __restrict__ bias,
              float* __restrict__ C)
{
    gemm_body<true>(g_ctx, B, bias, C, SQ, DM, DM);
}

// ---------------------------------------------------------------------------
// Flash attention v2, causal. Br=Bc=128, 256 threads (16x16).
// S-phase: 8x8 micro-tile (split 4+4), PV-phase: 8x4.
// Q,K stored transposed [d][row] stride 132 -> vector LDS both fragments.
// Q pre-scaled by 1/sqrt(HD). Reversed qb order for load balance.
// Smem: QT 64x132 | KT 64x132 | Vs 128x68 | Ps 128x132  = 169984 B
// ---------------------------------------------------------------------------
#define ATTN_SMEM (int)((64*132 + 64*132 + 128*68 + 128*132) * sizeof(float))

__global__ __launch_bounds__(256)
void attn_kernel()
{
    extern __shared__ float sm[];
    float* QT = sm;                       // [d][row] stride 132
    float* KT = sm + 64 * 132;            // [d][col] stride 132
    float* Vs = sm + 2 * 64 * 132;        // [row][d] stride 68
    float* Ps = sm + 2 * 64 * 132 + 128 * 68;  // [row][col] stride 132

    const int qb  = gridDim.x - 1 - blockIdx.x;   // reversed: long CTAs first
    const int h   = blockIdx.y;
    const int tid = threadIdx.x;
    const int tx  = tid & 15;
    const int ty  = tid >> 4;
    const int hoff = h * HDIM;

    // loader mapping: 128 rows, 2 column-halves of 32
    const int lr   = tid & 127;
    const int lhal = (tid >> 7) * 32;     // 0 or 32

    const float* q = g_q;
    const float* k = g_k;
    const float* v = g_v;

    // Load Q tile transposed + pre-scale by 1/sqrt(64)
    {
        const float* qrow = q + (size_t)(qb * 128 + lr) * DM + hoff + lhal;
#pragma unroll
        for (int f = 0; f < 8; f++) {
            float4 t = *(const float4*)(qrow + f * 4);
            int d = lhal + f * 4;
            QT[(d + 0) * 132 + lr] = t.x * 0.125f;
            QT[(d + 1) * 132 + lr] = t.y * 0.125f;
            QT[(d + 2) * 132 + lr] = t.z * 0.125f;
            QT[(d + 3) * 132 + lr] = t.w * 0.125f;
        }
    }

    float acc[8][4];
#pragma unroll
    for (int i = 0; i < 8; i++)
#pragma unroll
        for (int j = 0; j < 4; j++) acc[i][j] = 0.f;
    float mi[8], li[8];
#pragma unroll
    for (int i = 0; i < 8; i++) { mi[i] = -1e30f; li[i] = 0.f; }

    const int r0 = ty * 4;        // first row group
    const int c0 = tx * 4;        // first col group

    for (int kb = 0; kb <= qb; kb++) {
        __syncthreads();   // prev-iter KT/Vs/Ps reads complete (also Q visible on iter 0)

        // Load K transposed and V natural
        {
            const float* krow = k + (size_t)(kb * 128 + lr) * DM + hoff + lhal;
            const float* vrow = v + (size_t)(kb * 128 + lr) * DM + hoff + lhal;
#pragma unroll
            for (int f = 0; f < 8; f++) {
                float4 t = *(const float4*)(krow + f * 4);
                int d = lhal + f * 4;
                KT[(d + 0) * 132 + lr] = t.x;
                KT[(d + 1) * 132 + lr] = t.y;
                KT[(d + 2) * 132 + lr] = t.z;
                KT[(d + 3) * 132 + lr] = t.w;
                float4 tv = *(const float4*)(vrow + f * 4);
                *(float4*)&Vs[lr * 68 + lhal + f * 4] = tv;
            }
        }
        __syncthreads();

        // S = Q^T' K  (128x128), 8x8 per thread, split 4+4
        float s[8][8];
#pragma unroll
        for (int i = 0; i < 8; i++)
#pragma unroll
            for (int j = 0; j < 8; j++) s[i][j] = 0.f;

#pragma unroll 4
        for (int d = 0; d < 64; d++) {
            float4 a0 = *(const float4*)&QT[d * 132 + r0];
            float4 a1 = *(const float4*)&QT[d * 132 + 64 + r0];
            float4 b0 = *(const float4*)&KT[d * 132 + c0];
            float4 b1 = *(const float4*)&KT[d * 132 + 64 + c0];
            float av[8] = {a0.x, a0.y, a0.z, a0.w, a1.x, a1.y, a1.z, a1.w};
            float bv[8] = {b0.x, b0.y, b0.z, b0.w, b1.x, b1.y, b1.z, b1.w};
#pragma unroll
            for (int i = 0; i < 8; i++)
#pragma unroll
                for (int j = 0; j < 8; j++)
                    s[i][j] += av[i] * bv[j];
        }

        const bool diag = (kb == qb);

        // Online softmax per owned row
#pragma unroll
        for (int i = 0; i < 8; i++) {
            int ri = (i < 4) ? (r0 + i) : (64 + r0 + i - 4);   // local row
            if (diag) {
#pragma unroll
                for (int j = 0; j < 8; j++) {
                    int cj = (j < 4) ? (c0 + j) : (64 + c0 + j - 4);
                    if (cj > ri) s[i][j] = -1e30f;
                }
            }
            float rm = s[i][0];
#pragma unroll
            for (int j = 1; j < 8; j++) rm = fmaxf(rm, s[i][j]);
#pragma unroll
            for (int off = 8; off; off >>= 1)
                rm = fmaxf(rm, __shfl_xor_sync(0xffffffffu, rm, off));
            float mnew = fmaxf(mi[i], rm);
            float rs = 0.f;
#pragma unroll
            for (int j = 0; j < 8; j++) {
                s[i][j] = __expf(s[i][j] - mnew);
                rs += s[i][j];
            }
#pragma unroll
            for (int off = 8; off; off >>= 1)
                rs += __shfl_xor_sync(0xffffffffu, rs, off);
            float corr = __expf(mi[i] - mnew);
            li[i] = li[i] * corr + rs;
#pragma unroll
            for (int j = 0; j < 4; j++) acc[i][j] *= corr;
            mi[i] = mnew;
            float4 p0; p0.x = s[i][0]; p0.y = s[i][1]; p0.z = s[i][2]; p0.w = s[i][3];
            float4 p1; p1.x = s[i][4]; p1.y = s[i][5]; p1.z = s[i][6]; p1.w = s[i][7];
            *(float4*)&Ps[ri * 132 + c0]      = p0;
            *(float4*)&Ps[ri * 132 + 64 + c0] = p1;
        }
        __syncthreads();   // Ps complete before PV reads

        // O += P V   (128 kk), 8 rows x 4 cols per thread
#pragma unroll 4
        for (int kk = 0; kk < 128; kk++) {
            float4 vv = *(const float4*)&Vs[kk * 68 + c0];
            float p[8];
#pragma unroll
            for (int i = 0; i < 4; i++) {
                p[i]     = Ps[(r0 + i) * 132 + kk];
                p[i + 4] = Ps[(64 + r0 + i) * 132 + kk];
            }
#pragma unroll
            for (int i = 0; i < 8; i++) {
                acc[i][0] += p[i] * vv.x;
                acc[i][1] += p[i] * vv.y;
                acc[i][2] += p[i] * vv.z;
                acc[i][3] += p[i] * vv.w;
            }
        }
    }

    // Finalize
    float* ctx = g_ctx;
#pragma unroll
    for (int i = 0; i < 8; i++) {
        int ri = (i < 4) ? (r0 + i) : (64 + r0 + i - 4);
        float inv = 1.0f / li[i];
        float4 o;
        o.x = acc[i][0] * inv;
        o.y = acc[i][1] * inv;
        o.z = acc[i][2] * inv;
        o.w = acc[i][3] * inv;
        *(float4*)(ctx + (size_t)(qb * 128 + ri) * DM + hoff + c0) = o;
    }
}

// ---------------------------------------------------------------------------
extern "C" void kernel_launch(void* const* d_in, const int* in_sizes, int n_in,
                              void* d_out, int out_size)
{
    const float* x  = (const float*)d_in[0];
    const float* Wq = (const float*)d_in[1];
    const float* Wk = (const float*)d_in[2];
    const float* Wv = (const float*)d_in[3];
    const float* Wo = (const float*)d_in[4];
    const float* bo = (const float*)d_in[5];
    float* out = (float*)d_out;

    dim3 gg(DM / 128, SQ / 128);   // (8, 32)
    gemm_proj<0><<<gg, 256>>>(x, Wq);
    gemm_proj<1><<<gg, 256>>>(x, Wk);
    gemm_proj<2><<<gg, 256>>>(x, Wv);

    cudaFuncSetAttribute(attn_kernel, cudaFuncAttributeMaxDynamicSharedMemorySize, ATTN_SMEM);
    attn_kernel<<<dim3(SQ / 128, NH), 256, ATTN_SMEM>>>();

    gemm_out<<<gg, 256>>>(Wo, bo, out);
}

// round 6
// speedup vs baseline: 1.1531x; 1.0998x over previous
#include <cuda_runtime.h>
#include <cuda_bf16.h>
#include <cstdint>

// Problem constants
#define SQ   4096
#define DM   1024
#define NH   16
#define HDIM 64

// ---------------------------------------------------------------------------
// Scratch (allocation-free rule: __device__ globals)
// ---------------------------------------------------------------------------
__device__ float g_q[SQ * DM];
__device__ float g_k[SQ * DM];
__device__ float g_v[SQ * DM];
__device__ float g_ctx[SQ * DM];

__device__ __align__(16) __nv_bfloat16 g_xh[SQ * DM];
__device__ __align__(16) __nv_bfloat16 g_xl[SQ * DM];
__device__ __align__(16) __nv_bfloat16 g_wh[4][DM * DM];
__device__ __align__(16) __nv_bfloat16 g_wl[4][DM * DM];
__device__ __align__(16) __nv_bfloat16 g_ch[SQ * DM];
__device__ __align__(16) __nv_bfloat16 g_cl[SQ * DM];

// ---------------------------------------------------------------------------
// warp-level bf16 MMA (legacy HMMA path — valid on compute_103, no 'a' feature)
// ---------------------------------------------------------------------------
__device__ __forceinline__ void mma16816(float* c, const uint32_t* a, const uint32_t* b)
{
    asm volatile(
        "mma.sync.aligned.m16n8k16.row.col.f32.bf16.bf16.f32 "
        "{%0,%1,%2,%3}, {%4,%5,%6,%7}, {%8,%9}, {%0,%1,%2,%3};\n"
        : "+f"(c[0]), "+f"(c[1]), "+f"(c[2]), "+f"(c[3])
        : "r"(a[0]), "r"(a[1]), "r"(a[2]), "r"(a[3]), "r"(b[0]), "r"(b[1]));
}

// ---------------------------------------------------------------------------
// fp32 -> bf16 hi/lo splitter. dst: 0=x, 1..4=W[0..3], 5=ctx (src=g_ctx)
// ---------------------------------------------------------------------------
__global__ void split_kernel(const float* __restrict__ src, int dst, int n2)
{
    __nv_bfloat16 *hi, *lo;
    switch (dst) {
        case 0: hi = g_xh;    lo = g_xl;    break;
        case 1: hi = g_wh[0]; lo = g_wl[0]; break;
        case 2: hi = g_wh[1]; lo = g_wl[1]; break;
        case 3: hi = g_wh[2]; lo = g_wl[2]; break;
        case 4: hi = g_wh[3]; lo = g_wl[3]; break;
        default: hi = g_ch;   lo = g_cl;    src = g_ctx; break;
    }
    int i = blockIdx.x * blockDim.x + threadIdx.x;
    if (i >= n2) return;
    float2 v = ((const float2*)src)[i];
    __nv_bfloat16 h0 = __float2bfloat16(v.x);
    __nv_bfloat16 h1 = __float2bfloat16(v.y);
    __nv_bfloat16 l0 = __float2bfloat16(v.x - __bfloat162float(h0));
    __nv_bfloat16 l1 = __float2bfloat16(v.y - __bfloat162float(h1));
    ((__nv_bfloat162*)hi)[i] = __halves2bfloat162(h0, h1);
    ((__nv_bfloat162*)lo)[i] = __halves2bfloat162(l0, l1);
}

// ---------------------------------------------------------------------------
// HMMA GEMM: C[4096,1024] = A[4096,1024] * B[1024,1024]^T (+bias)
// bf16 split: C = Ah*Bh + Ah*Bl + Al*Bh, fp32 accumulators.
// CTA 128x128, BK=16, 8 warps (2x4), warp tile 64x32, m16n8k16 frags.
// Smem rows stride 40 bf16 (80B): conflict-free fragment LDS.
// Double-buffered smem + register prefetch.
// ---------------------------------------------------------------------------
#define GSTR 40                       // smem row stride in bf16
#define GARR (128 * GSTR)             // one array: 5120 bf16
#define TCG_SMEM (int)(2 * 4 * GARR * sizeof(__nv_bfloat16))   // 81920 B

__global__ __launch_bounds__(256, 1)
void tc_gemm(int asel, int wsel, int csel, float* Cparam, const float* bias)
{
    extern __shared__ __nv_bfloat16 smem[];   // [2 bufs][4 arrays][GARR]

    const __nv_bfloat16* GAh = asel ? g_ch : g_xh;
    const __nv_bfloat16* GAl = asel ? g_cl : g_xl;
    const __nv_bfloat16* GBh = g_wh[wsel];
    const __nv_bfloat16* GBl = g_wl[wsel];
    float* C = (csel == 0) ? g_q : (csel == 1) ? g_k : (csel == 2) ? g_v : Cparam;

    const int tid  = threadIdx.x;
    const int wid  = tid >> 5;
    const int lane = tid & 31;
    const int wm   = wid >> 2;        // 0..1
    const int wn   = wid & 3;         // 0..3
    const int lr4  = lane >> 2;       // 0..7
    const int kq   = lane & 3;        // 0..3
    const int m0   = blockIdx.y * 128;
    const int n0   = blockIdx.x * 128;

    // loader mapping: 256 threads cover 128 rows x 2 k-chunks of 8 bf16
    const int row = tid >> 1;
    const int kc  = tid & 1;
    const size_t gA = (size_t)(m0 + row) * DM + kc * 8;
    const size_t gB = (size_t)(n0 + row) * DM + kc * 8;
    const int so = row * GSTR + kc * 8;   // bf16 index into one smem array

    float c[4][4][4];
#pragma unroll
    for (int i = 0; i < 4; i++)
#pragma unroll
        for (int j = 0; j < 4; j++)
#pragma unroll
            for (int e = 0; e < 4; e++) c[i][j][e] = 0.f;

    // Prologue: stage 0
    {
        uint4 va = *(const uint4*)(GAh + gA);
        uint4 vb = *(const uint4*)(GAl + gA);
        uint4 vc = *(const uint4*)(GBh + gB);
        uint4 vd = *(const uint4*)(GBl + gB);
        *(uint4*)(smem + 0 * GARR + so) = va;
        *(uint4*)(smem + 1 * GARR + so) = vb;
        *(uint4*)(smem + 2 * GARR + so) = vc;
        *(uint4*)(smem + 3 * GARR + so) = vd;
    }
    __syncthreads();

    int b = 0;
    uint4 pa, pl, pb, pd;
    for (int t = 0; t < 64; t++) {
        if (t < 63) {
            size_t ko = (size_t)(t + 1) * 16;
            pa = *(const uint4*)(GAh + gA + ko);
            pl = *(const uint4*)(GAl + gA + ko);
            pb = *(const uint4*)(GBh + gB + ko);
            pd = *(const uint4*)(GBl + gB + ko);
        }

        const uint32_t* sAh = (const uint32_t*)(smem + (b * 4 + 0) * GARR);
        const uint32_t* sAl = (const uint32_t*)(smem + (b * 4 + 1) * GARR);
        const uint32_t* sBh = (const uint32_t*)(smem + (b * 4 + 2) * GARR);
        const uint32_t* sBl = (const uint32_t*)(smem + (b * 4 + 3) * GARR);

        uint32_t ah[4][4], al[4][4], bh[4][2], bl[4][2];
#pragma unroll
        for (int i = 0; i < 4; i++) {
            int base = (wm * 64 + i * 16 + lr4) * (GSTR / 2) + kq;
            ah[i][0] = sAh[base];
            ah[i][1] = sAh[base + 8 * (GSTR / 2)];
            ah[i][2] = sAh[base + 4];
            ah[i][3] = sAh[base + 8 * (GSTR / 2) + 4];
            al[i][0] = sAl[base];
            al[i][1] = sAl[base + 8 * (GSTR / 2)];
            al[i][2] = sAl[base + 4];
            al[i][3] = sAl[base + 8 * (GSTR / 2) + 4];
        }
#pragma unroll
        for (int j = 0; j < 4; j++) {
            int nb = (wn * 32 + j * 8 + lr4) * (GSTR / 2) + kq;
            bh[j][0] = sBh[nb];
            bh[j][1] = sBh[nb + 4];
            bl[j][0] = sBl[nb];
            bl[j][1] = sBl[nb + 4];
        }

#pragma unroll
        for (int i = 0; i < 4; i++)
#pragma unroll
            for (int j = 0; j < 4; j++) {
                mma16816(c[i][j], ah[i], bh[j]);
                mma16816(c[i][j], ah[i], bl[j]);
                mma16816(c[i][j], al[i], bh[j]);
            }

        if (t < 63) {
            int nbuf = b ^ 1;
            *(uint4*)(smem + (nbuf * 4 + 0) * GARR + so) = pa;
            *(uint4*)(smem + (nbuf * 4 + 1) * GARR + so) = pl;
            *(uint4*)(smem + (nbuf * 4 + 2) * GARR + so) = pb;
            *(uint4*)(smem + (nbuf * 4 + 3) * GARR + so) = pd;
            __syncthreads();
            b = nbuf;
        }
    }

    // Epilogue: c0,c1 -> (row, col..col+1), c2,c3 -> (row+8, ...)
#pragma unroll
    for (int i = 0; i < 4; i++) {
        int r = m0 + wm * 64 + i * 16 + lr4;
#pragma unroll
        for (int j = 0; j < 4; j++) {
            int col = n0 + wn * 32 + j * 8 + kq * 2;
            float bx = 0.f, by = 0.f;
            if (bias) { bx = bias[col]; by = bias[col + 1]; }
            float2 v0 = make_float2(c[i][j][0] + bx, c[i][j][1] + by);
            float2 v1 = make_float2(c[i][j][2] + bx, c[i][j][3] + by);
            *(float2*)(C + (size_t)r * DM + col)       = v0;
            *(float2*)(C + (size_t)(r + 8) * DM + col) = v1;
        }
    }
}

// ---------------------------------------------------------------------------
// Flash attention v2, causal (unchanged from R4 passing version).
// Br=Bc=128, 256 threads, S: 8x8 split 4+4, PV: 8x4. Q pre-scaled.
// ---------------------------------------------------------------------------
#define ATTN_SMEM (int)((64*132 + 64*132 + 128*68 + 128*132) * sizeof(float))

__global__ __launch_bounds__(256)
void attn_kernel()
{
    extern __shared__ float sm[];
    float* QT = sm;                       // [d][row] stride 132
    float* KT = sm + 64 * 132;            // [d][col] stride 132
    float* Vs = sm + 2 * 64 * 132;        // [row][d] stride 68
    float* Ps = sm + 2 * 64 * 132 + 128 * 68;  // [row][col] stride 132

    const int qb  = gridDim.x - 1 - blockIdx.x;   // reversed: long CTAs first
    const int h   = blockIdx.y;
    const int tid = threadIdx.x;
    const int tx  = tid & 15;
    const int ty  = tid >> 4;
    const int hoff = h * HDIM;

    const int lr   = tid & 127;
    const int lhal = (tid >> 7) * 32;     // 0 or 32

    const float* q = g_q;
    const float* k = g_k;
    const float* v = g_v;

    {
        const float* qrow = q + (size_t)(qb * 128 + lr) * DM + hoff + lhal;
#pragma unroll
        for (int f = 0; f < 8; f++) {
            float4 t = *(const float4*)(qrow + f * 4);
            int d = lhal + f * 4;
            QT[(d + 0) * 132 + lr] = t.x * 0.125f;
            QT[(d + 1) * 132 + lr] = t.y * 0.125f;
            QT[(d + 2) * 132 + lr] = t.z * 0.125f;
            QT[(d + 3) * 132 + lr] = t.w * 0.125f;
        }
    }

    float acc[8][4];
#pragma unroll
    for (int i = 0; i < 8; i++)
#pragma unroll
        for (int j = 0; j < 4; j++) acc[i][j] = 0.f;
    float mi[8], li[8];
#pragma unroll
    for (int i = 0; i < 8; i++) { mi[i] = -1e30f; li[i] = 0.f; }

    const int r0 = ty * 4;
    const int c0 = tx * 4;

    for (int kb = 0; kb <= qb; kb++) {
        __syncthreads();

        {
            const float* krow = k + (size_t)(kb * 128 + lr) * DM + hoff + lhal;
            const float* vrow = v + (size_t)(kb * 128 + lr) * DM + hoff + lhal;
#pragma unroll
            for (int f = 0; f < 8; f++) {
                float4 t = *(const float4*)(krow + f * 4);
                int d = lhal + f * 4;
                KT[(d + 0) * 132 + lr] = t.x;
                KT[(d + 1) * 132 + lr] = t.y;
                KT[(d + 2) * 132 + lr] = t.z;
                KT[(d + 3) * 132 + lr] = t.w;
                float4 tv = *(const float4*)(vrow + f * 4);
                *(float4*)&Vs[lr * 68 + lhal + f * 4] = tv;
            }
        }
        __syncthreads();

        float s[8][8];
#pragma unroll
        for (int i = 0; i < 8; i++)
#pragma unroll
            for (int j = 0; j < 8; j++) s[i][j] = 0.f;

#pragma unroll 4
        for (int d = 0; d < 64; d++) {
            float4 a0 = *(const float4*)&QT[d * 132 + r0];
            float4 a1 = *(const float4*)&QT[d * 132 + 64 + r0];
            float4 b0 = *(const float4*)&KT[d * 132 + c0];
            float4 b1 = *(const float4*)&KT[d * 132 + 64 + c0];
            float av[8] = {a0.x, a0.y, a0.z, a0.w, a1.x, a1.y, a1.z, a1.w};
            float bv[8] = {b0.x, b0.y, b0.z, b0.w, b1.x, b1.y, b1.z, b1.w};
#pragma unroll
            for (int i = 0; i < 8; i++)
#pragma unroll
                for (int j = 0; j < 8; j++)
                    s[i][j] += av[i] * bv[j];
        }

        const bool diag = (kb == qb);

#pragma unroll
        for (int i = 0; i < 8; i++) {
            int ri = (i < 4) ? (r0 + i) : (64 + r0 + i - 4);
            if (diag) {
#pragma unroll
                for (int j = 0; j < 8; j++) {
                    int cj = (j < 4) ? (c0 + j) : (64 + c0 + j - 4);
                    if (cj > ri) s[i][j] = -1e30f;
                }
            }
            float rm = s[i][0];
#pragma unroll
            for (int j = 1; j < 8; j++) rm = fmaxf(rm, s[i][j]);
#pragma unroll
            for (int off = 8; off; off >>= 1)
                rm = fmaxf(rm, __shfl_xor_sync(0xffffffffu, rm, off));
            float mnew = fmaxf(mi[i], rm);
            float rs = 0.f;
#pragma unroll
            for (int j = 0; j < 8; j++) {
                s[i][j] = __expf(s[i][j] - mnew);
                rs += s[i][j];
            }
#pragma unroll
            for (int off = 8; off; off >>= 1)
                rs += __shfl_xor_sync(0xffffffffu, rs, off);
            float corr = __expf(mi[i] - mnew);
            li[i] = li[i] * corr + rs;
#pragma unroll
            for (int j = 0; j < 4; j++) acc[i][j] *= corr;
            mi[i] = mnew;
            float4 p0; p0.x = s[i][0]; p0.y = s[i][1]; p0.z = s[i][2]; p0.w = s[i][3];
            float4 p1; p1.x = s[i][4]; p1.y = s[i][5]; p1.z = s[i][6]; p1.w = s[i][7];
            *(float4*)&Ps[ri * 132 + c0]      = p0;
            *(float4*)&Ps[ri * 132 + 64 + c0] = p1;
        }
        __syncthreads();

#pragma unroll 4
        for (int kk = 0; kk < 128; kk++) {
            float4 vv = *(const float4*)&Vs[kk * 68 + c0];
            float p[8];
#pragma unroll
            for (int i = 0; i < 4; i++) {
                p[i]     = Ps[(r0 + i) * 132 + kk];
                p[i + 4] = Ps[(64 + r0 + i) * 132 + kk];
            }
#pragma unroll
            for (int i = 0; i < 8; i++) {
                acc[i][0] += p[i] * vv.x;
                acc[i][1] += p[i] * vv.y;
                acc[i][2] += p[i] * vv.z;
                acc[i][3] += p[i] * vv.w;
            }
        }
    }

    float* ctx = g_ctx;
#pragma unroll
    for (int i = 0; i < 8; i++) {
        int ri = (i < 4) ? (r0 + i) : (64 + r0 + i - 4);
        float inv = 1.0f / li[i];
        float4 o;
        o.x = acc[i][0] * inv;
        o.y = acc[i][1] * inv;
        o.z = acc[i][2] * inv;
        o.w = acc[i][3] * inv;
        *(float4*)(ctx + (size_t)(qb * 128 + ri) * DM + hoff + c0) = o;
    }
}

// ---------------------------------------------------------------------------
extern "C" void kernel_launch(void* const* d_in, const int* in_sizes, int n_in,
                              void* d_out, int out_size)
{
    const float* x  = (const float*)d_in[0];
    const float* Wq = (const float*)d_in[1];
    const float* Wk = (const float*)d_in[2];
    const float* Wv = (const float*)d_in[3];
    const float* Wo = (const float*)d_in[4];
    const float* bo = (const float*)d_in[5];
    float* out = (float*)d_out;

    cudaFuncSetAttribute(tc_gemm, cudaFuncAttributeMaxDynamicSharedMemorySize, TCG_SMEM);
    cudaFuncSetAttribute(attn_kernel, cudaFuncAttributeMaxDynamicSharedMemorySize, ATTN_SMEM);

    const int n2x = SQ * DM / 2;   // float2 units
    const int n2w = DM * DM / 2;

    split_kernel<<<n2x / 256, 256>>>(x,  0, n2x);
    split_kernel<<<n2w / 256, 256>>>(Wq, 1, n2w);
    split_kernel<<<n2w / 256, 256>>>(Wk, 2, n2w);
    split_kernel<<<n2w / 256, 256>>>(Wv, 3, n2w);
    split_kernel<<<n2w / 256, 256>>>(Wo, 4, n2w);

    dim3 gg(DM / 128, SQ / 128);   // (8, 32)
    tc_gemm<<<gg, 256, TCG_SMEM>>>(0, 0, 0, nullptr, nullptr);  // Q
    tc_gemm<<<gg, 256, TCG_SMEM>>>(0, 1, 1, nullptr, nullptr);  // K
    tc_gemm<<<gg, 256, TCG_SMEM>>>(0, 2, 2, nullptr, nullptr);  // V

    attn_kernel<<<dim3(SQ / 128, NH), 256, ATTN_SMEM>>>();

    split_kernel<<<n2x / 256, 256>>>(nullptr, 5, n2x);          // ctx -> hi/lo
    tc_gemm<<<gg, 256, TCG_SMEM>>>(1, 3, 3, out, bo);           // out proj + bias
}

// round 8
// speedup vs baseline: 2.2262x; 1.9306x over previous
#include <cuda_runtime.h>
#include <cuda_bf16.h>
#include <cstdint>

// Problem constants
#define SQ   4096
#define DM   1024
#define NH   16
#define HDIM 64

// ---------------------------------------------------------------------------
// Scratch (allocation-free rule: __device__ globals) — all bf16 hi/lo pairs
// ---------------------------------------------------------------------------
__device__ __align__(16) __nv_bfloat16 g_xh[SQ * DM];
__device__ __align__(16) __nv_bfloat16 g_xl[SQ * DM];
__device__ __align__(16) __nv_bfloat16 g_wh[4][DM * DM];
__device__ __align__(16) __nv_bfloat16 g_wl[4][DM * DM];
__device__ __align__(16) __nv_bfloat16 g_qh[SQ * DM];   // pre-scaled by 0.125
__device__ __align__(16) __nv_bfloat16 g_ql[SQ * DM];
__device__ __align__(16) __nv_bfloat16 g_kh[SQ * DM];
__device__ __align__(16) __nv_bfloat16 g_kl[SQ * DM];
__device__ __align__(16) __nv_bfloat16 g_vh[SQ * DM];
__device__ __align__(16) __nv_bfloat16 g_vl[SQ * DM];
__device__ __align__(16) __nv_bfloat16 g_ch[SQ * DM];
__device__ __align__(16) __nv_bfloat16 g_cl[SQ * DM];

// ---------------------------------------------------------------------------
// PTX helpers (legacy / non-'a' instructions only: HMMA, ldmatrix, cp.async)
// ---------------------------------------------------------------------------
__device__ __forceinline__ uint32_t smem_to_u32(const void* p) {
    uint32_t a;
    asm("{ .reg .u64 t; cvta.to.shared.u64 t, %1; cvt.u32.u64 %0, t; }"
        : "=r"(a) : "l"(p));
    return a;
}

__device__ __forceinline__ void mma16816(float* c, const uint32_t* a, const uint32_t* b)
{
    asm volatile(
        "mma.sync.aligned.m16n8k16.row.col.f32.bf16.bf16.f32 "
        "{%0,%1,%2,%3}, {%4,%5,%6,%7}, {%8,%9}, {%0,%1,%2,%3};\n"
        : "+f"(c[0]), "+f"(c[1]), "+f"(c[2]), "+f"(c[3])
        : "r"(a[0]), "r"(a[1]), "r"(a[2]), "r"(a[3]), "r"(b[0]), "r"(b[1]));
}

__device__ __forceinline__ void ldsm4(uint32_t* r, uint32_t addr)
{
    asm volatile("ldmatrix.sync.aligned.m8n8.x4.shared.b16 {%0,%1,%2,%3}, [%4];"
        : "=r"(r[0]), "=r"(r[1]), "=r"(r[2]), "=r"(r[3]) : "r"(addr));
}

__device__ __forceinline__ void ldsm4t(uint32_t* r, uint32_t addr)
{
    asm volatile("ldmatrix.sync.aligned.m8n8.x4.trans.shared.b16 {%0,%1,%2,%3}, [%4];"
        : "=r"(r[0]), "=r"(r[1]), "=r"(r[2]), "=r"(r[3]) : "r"(addr));
}

__device__ __forceinline__ void cp16(uint32_t dst, const void* src)
{
    asm volatile("cp.async.ca.shared.global [%0], [%1], 16;" :: "r"(dst), "l"(src));
}
#define CP_COMMIT() asm volatile("cp.async.commit_group;" ::: "memory")
#define CP_WAIT0()  asm volatile("cp.async.wait_group 0;" ::: "memory")
#define CP_WAIT1()  asm volatile("cp.async.wait_group 1;" ::: "memory")

__device__ __forceinline__ uint32_t packbf(float lo, float hi)
{
    uint32_t r;
    asm("cvt.rn.bf16x2.f32 %0, %1, %2;" : "=r"(r) : "f"(hi), "f"(lo));
    return r;
}

// ---------------------------------------------------------------------------
// fp32 -> bf16 hi/lo splitter. dst: 0=x, 1..4=W[0..3]
// ---------------------------------------------------------------------------
__global__ void split_kernel(const float* __restrict__ src, int dst, int n2)
{
    __nv_bfloat16 *hi, *lo;
    switch (dst) {
        case 0: hi = g_xh;    lo = g_xl;    break;
        case 1: hi = g_wh[0]; lo = g_wl[0]; break;
        case 2: hi = g_wh[1]; lo = g_wl[1]; break;
        case 3: hi = g_wh[2]; lo = g_wl[2]; break;
        default: hi = g_wh[3]; lo = g_wl[3]; break;
    }
    int i = blockIdx.x * blockDim.x + threadIdx.x;
    if (i >= n2) return;
    float2 v = ((const float2*)src)[i];
    __nv_bfloat16 h0 = __float2bfloat16(v.x);
    __nv_bfloat16 h1 = __float2bfloat16(v.y);
    __nv_bfloat16 l0 = __float2bfloat16(v.x - __bfloat162float(h0));
    __nv_bfloat16 l1 = __float2bfloat16(v.y - __bfloat162float(h1));
    ((__nv_bfloat162*)hi)[i] = __halves2bfloat162(h0, h1);
    ((__nv_bfloat162*)lo)[i] = __halves2bfloat162(l0, l1);
}

// ---------------------------------------------------------------------------
// HMMA GEMM: C[4096,1024] = A[4096,1024] * B[1024,1024]^T
// csel 0: -> (g_qh,g_ql) scaled 0.125 | 1: (g_kh,g_kl) | 2: (g_vh,g_vl)
// csel 3: fp32 + bias -> Cparam
// ---------------------------------------------------------------------------
#define GSTR 40
#define GARR (128 * GSTR)
#define TCG_SMEM (int)(2 * 4 * GARR * sizeof(__nv_bfloat16))   // 81920 B

__global__ __launch_bounds__(256, 1)
void tc_gemm(int asel, int wsel, int csel, float* Cparam, const float* bias)
{
    extern __shared__ __nv_bfloat16 smem[];

    const __nv_bfloat16* GAh = asel ? g_ch : g_xh;
    const __nv_bfloat16* GAl = asel ? g_cl : g_xl;
    const __nv_bfloat16* GBh = g_wh[wsel];
    const __nv_bfloat16* GBl = g_wl[wsel];

    const int tid  = threadIdx.x;
    const int wid  = tid >> 5;
    const int lane = tid & 31;
    const int wm   = wid >> 2;
    const int wn   = wid & 3;
    const int lr4  = lane >> 2;
    const int kq   = lane & 3;
    const int m0   = blockIdx.y * 128;
    const int n0   = blockIdx.x * 128;

    const int row = tid >> 1;
    const int kc  = tid & 1;
    const size_t gA = (size_t)(m0 + row) * DM + kc * 8;
    const size_t gB = (size_t)(n0 + row) * DM + kc * 8;
    const int so = row * GSTR + kc * 8;

    float c[4][4][4];
#pragma unroll
    for (int i = 0; i < 4; i++)
#pragma unroll
        for (int j = 0; j < 4; j++)
#pragma unroll
            for (int e = 0; e < 4; e++) c[i][j][e] = 0.f;

    {
        uint4 va = *(const uint4*)(GAh + gA);
        uint4 vb = *(const uint4*)(GAl + gA);
        uint4 vc = *(const uint4*)(GBh + gB);
        uint4 vd = *(const uint4*)(GBl + gB);
        *(uint4*)(smem + 0 * GARR + so) = va;
        *(uint4*)(smem + 1 * GARR + so) = vb;
        *(uint4*)(smem + 2 * GARR + so) = vc;
        *(uint4*)(smem + 3 * GARR + so) = vd;
    }
    __syncthreads();

    int b = 0;
    uint4 pa, pl, pb, pd;
    for (int t = 0; t < 64; t++) {
        if (t < 63) {
            size_t ko = (size_t)(t + 1) * 16;
            pa = *(const uint4*)(GAh + gA + ko);
            pl = *(const uint4*)(GAl + gA + ko);
            pb = *(const uint4*)(GBh + gB + ko);
            pd = *(const uint4*)(GBl + gB + ko);
        }

        const uint32_t* sAh = (const uint32_t*)(smem + (b * 4 + 0) * GARR);
        const uint32_t* sAl = (const uint32_t*)(smem + (b * 4 + 1) * GARR);
        const uint32_t* sBh = (const uint32_t*)(smem + (b * 4 + 2) * GARR);
        const uint32_t* sBl = (const uint32_t*)(smem + (b * 4 + 3) * GARR);

        uint32_t ah[4][4], al[4][4], bh[4][2], bl[4][2];
#pragma unroll
        for (int i = 0; i < 4; i++) {
            int base = (wm * 64 + i * 16 + lr4) * (GSTR / 2) + kq;
            ah[i][0] = sAh[base];
            ah[i][1] = sAh[base + 8 * (GSTR / 2)];
            ah[i][2] = sAh[base + 4];
            ah[i][3] = sAh[base + 8 * (GSTR / 2) + 4];
            al[i][0] = sAl[base];
            al[i][1] = sAl[base + 8 * (GSTR / 2)];
            al[i][2] = sAl[base + 4];
            al[i][3] = sAl[base + 8 * (GSTR / 2) + 4];
        }
#pragma unroll
        for (int j = 0; j < 4; j++) {
            int nb = (wn * 32 + j * 8 + lr4) * (GSTR / 2) + kq;
            bh[j][0] = sBh[nb];
            bh[j][1] = sBh[nb + 4];
            bl[j][0] = sBl[nb];
            bl[j][1] = sBl[nb + 4];
        }

#pragma unroll
        for (int i = 0; i < 4; i++)
#pragma unroll
            for (int j = 0; j < 4; j++) {
                mma16816(c[i][j], ah[i], bh[j]);
                mma16816(c[i][j], ah[i], bl[j]);
                mma16816(c[i][j], al[i], bh[j]);
            }

        if (t < 63) {
            int nbuf = b ^ 1;
            *(uint4*)(smem + (nbuf * 4 + 0) * GARR + so) = pa;
            *(uint4*)(smem + (nbuf * 4 + 1) * GARR + so) = pl;
            *(uint4*)(smem + (nbuf * 4 + 2) * GARR + so) = pb;
            *(uint4*)(smem + (nbuf * 4 + 3) * GARR + so) = pd;
            __syncthreads();
            b = nbuf;
        }
    }

    if (csel < 3) {
        __nv_bfloat16* Hd = (csel == 0) ? g_qh : (csel == 1) ? g_kh : g_vh;
        __nv_bfloat16* Ld = (csel == 0) ? g_ql : (csel == 1) ? g_kl : g_vl;
        const float scale = (csel == 0) ? 0.125f : 1.0f;
#pragma unroll
        for (int i = 0; i < 4; i++) {
            int r = m0 + wm * 64 + i * 16 + lr4;
#pragma unroll
            for (int j = 0; j < 4; j++) {
                int col = n0 + wn * 32 + j * 8 + kq * 2;
#pragma unroll
                for (int half = 0; half < 2; half++) {
                    int rr = r + half * 8;
                    float v0 = c[i][j][half * 2 + 0] * scale;
                    float v1 = c[i][j][half * 2 + 1] * scale;
                    __nv_bfloat16 h0 = __float2bfloat16(v0);
                    __nv_bfloat16 h1 = __float2bfloat16(v1);
                    __nv_bfloat16 l0 = __float2bfloat16(v0 - __bfloat162float(h0));
                    __nv_bfloat16 l1 = __float2bfloat16(v1 - __bfloat162float(h1));
                    *(__nv_bfloat162*)&Hd[(size_t)rr * DM + col] = __halves2bfloat162(h0, h1);
                    *(__nv_bfloat162*)&Ld[(size_t)rr * DM + col] = __halves2bfloat162(l0, l1);
                }
            }
        }
    } else {
#pragma unroll
        for (int i = 0; i < 4; i++) {
            int r = m0 + wm * 64 + i * 16 + lr4;
#pragma unroll
            for (int j = 0; j < 4; j++) {
                int col = n0 + wn * 32 + j * 8 + kq * 2;
                float bx = bias[col], by = bias[col + 1];
                *(float2*)(Cparam + (size_t)r * DM + col)       = make_float2(c[i][j][0] + bx, c[i][j][1] + by);
                *(float2*)(Cparam + (size_t)(r + 8) * DM + col) = make_float2(c[i][j][2] + bx, c[i][j][3] + by);
            }
        }
    }
}

// ---------------------------------------------------------------------------
// MMA flash attention, causal. CTA = (128-query block, head). 8 warps x 16 rows.
// S = qh*kh + qh*kl + ql*kh  (Q pre-scaled);  O += ph*vh + ph*vl + pl*vh.
// Smem bf16 units: Qh[0], Ql[9216]; KV(buf,arr) = 18432 + buf*36864 + arr*9216
//   arr: 0=Kh 1=Kl 2=Vh 3=Vl; all tiles [128][72].
// cp.async double-buffered KV. Epilogue writes hi/lo ctx.
// ---------------------------------------------------------------------------
#define ASTR 72
#define ATILE (128 * ASTR)              // 9216 bf16
#define ATTN_SMEM (int)((2 * ATILE + 2 * 4 * ATILE) * sizeof(__nv_bfloat16))  // 184320 B

__device__ __forceinline__ void kv_load(uint32_t sbase, int tid, int kb, int buf, int hoff)
{
#pragma unroll
    for (int i = 0; i < 16; i++) {
        int id  = tid + 256 * i;
        int arr = id >> 10;
        int rem = id & 1023;
        int row = rem >> 3;
        int ch  = rem & 7;
        const __nv_bfloat16* src =
            ((arr == 0) ? g_kh : (arr == 1) ? g_kl : (arr == 2) ? g_vh : g_vl)
            + (size_t)(kb * 128 + row) * DM + hoff + ch * 8;
        uint32_t dst = sbase + (uint32_t)(18432 + buf * 36864 + arr * 9216 + row * ASTR + ch * 8) * 2;
        cp16(dst, src);
    }
}

__global__ __launch_bounds__(256, 1)
void attn_mma()
{
    extern __shared__ __nv_bfloat16 asm_sm[];
    const uint32_t sbase = smem_to_u32(asm_sm);

    const int qb   = gridDim.x - 1 - blockIdx.x;    // reversed: long CTAs first
    const int h    = blockIdx.y;
    const int hoff = h * HDIM;
    const int tid  = threadIdx.x;
    const int wid  = tid >> 5;
    const int lane = tid & 31;
    const int lr4  = lane >> 2;
    const int kq   = lane & 3;

    // Q load (cp.async): 2048 chunks
#pragma unroll
    for (int i = 0; i < 8; i++) {
        int id  = tid + 256 * i;
        int arr = id >> 10;
        int rem = id & 1023;
        int row = rem >> 3;
        int ch  = rem & 7;
        const __nv_bfloat16* src = (arr ? g_ql : g_qh)
            + (size_t)(qb * 128 + row) * DM + hoff + ch * 8;
        uint32_t dst = sbase + (uint32_t)(arr * 9216 + row * ASTR + ch * 8) * 2;
        cp16(dst, src);
    }
    kv_load(sbase, tid, 0, 0, hoff);
    CP_COMMIT();

    // per-lane ldmatrix address offsets (bf16 units)
    const uint32_t qoff = (uint32_t)((wid * 16 + (lane & 7) + ((lane >> 3) & 1) * 8) * ASTR
                                     + ((lane >> 4) & 1) * 8);
    const uint32_t koff = (uint32_t)(((lane & 7) + ((lane >> 4) & 1) * 8) * ASTR
                                     + ((lane >> 3) & 1) * 8);
    const uint32_t voff = (uint32_t)(((lane & 7) + ((lane >> 3) & 1) * 8) * ASTR
                                     + ((lane >> 4) & 1) * 8);

    float o[8][4];
#pragma unroll
    for (int i = 0; i < 8; i++)
#pragma unroll
        for (int e = 0; e < 4; e++) o[i][e] = 0.f;
    float m_lo = -1e30f, m_hi = -1e30f, l_lo = 0.f, l_hi = 0.f;

    for (int kb = 0; kb <= qb; kb++) {
        const int buf = kb & 1;
        if (kb < qb) {
            kv_load(sbase, tid, kb + 1, buf ^ 1, hoff);
            CP_COMMIT();
            CP_WAIT1();
        } else {
            CP_WAIT0();
        }
        __syncthreads();

        const uint32_t Qh_b = sbase;
        const uint32_t Ql_b = sbase + 9216 * 2;
        const uint32_t Kh_b = sbase + (uint32_t)(18432 + buf * 36864) * 2;
        const uint32_t Kl_b = Kh_b + 9216 * 2;
        const uint32_t Vh_b = Kh_b + 2 * 9216 * 2;
        const uint32_t Vl_b = Kh_b + 3 * 9216 * 2;

        // ---- S = Q K^T (warp: 16 x 128) ----
        float s[16][4];
#pragma unroll
        for (int j = 0; j < 16; j++)
#pragma unroll
            for (int e = 0; e < 4; e++) s[j][e] = 0.f;

#pragma unroll
        for (int ks = 0; ks < 4; ks++) {
            uint32_t ah[4], al[4];
            ldsm4(ah, Qh_b + (qoff + ks * 16) * 2);
            ldsm4(al, Ql_b + (qoff + ks * 16) * 2);
#pragma unroll
            for (int jp = 0; jp < 8; jp++) {
                uint32_t bh[4], bl[4];
                ldsm4(bh, Kh_b + (koff + jp * 16 * ASTR + ks * 16) * 2);
                ldsm4(bl, Kl_b + (koff + jp * 16 * ASTR + ks * 16) * 2);
                mma16816(s[2 * jp],     ah, bh);
                mma16816(s[2 * jp],     ah, bl);
                mma16816(s[2 * jp],     al, bh);
                mma16816(s[2 * jp + 1], ah, bh + 2);
                mma16816(s[2 * jp + 1], ah, bl + 2);
                mma16816(s[2 * jp + 1], al, bh + 2);
            }
        }

        // ---- causal mask (diag block only) ----
        if (kb == qb) {
            const int rl = wid * 16 + lr4;
#pragma unroll
            for (int j = 0; j < 16; j++) {
                int c0 = j * 8 + kq * 2;
                if (c0     > rl)     s[j][0] = -1e30f;
                if (c0 + 1 > rl)     s[j][1] = -1e30f;
                if (c0     > rl + 8) s[j][2] = -1e30f;
                if (c0 + 1 > rl + 8) s[j][3] = -1e30f;
            }
        }

        // ---- online softmax (rows lr4 / lr4+8 of warp tile) ----
        float bm_lo = -1e30f, bm_hi = -1e30f;
#pragma unroll
        for (int j = 0; j < 16; j++) {
            bm_lo = fmaxf(bm_lo, fmaxf(s[j][0], s[j][1]));
            bm_hi = fmaxf(bm_hi, fmaxf(s[j][2], s[j][3]));
        }
#pragma unroll
        for (int off = 1; off <= 2; off <<= 1) {
            bm_lo = fmaxf(bm_lo, __shfl_xor_sync(0xffffffffu, bm_lo, off));
            bm_hi = fmaxf(bm_hi, __shfl_xor_sync(0xffffffffu, bm_hi, off));
        }
        const float mn_lo = fmaxf(m_lo, bm_lo);
        const float mn_hi = fmaxf(m_hi, bm_hi);
        const float cor_lo = __expf(m_lo - mn_lo);
        const float cor_hi = __expf(m_hi - mn_hi);
        m_lo = mn_lo; m_hi = mn_hi;

        float sum_lo = 0.f, sum_hi = 0.f;
#pragma unroll
        for (int j = 0; j < 16; j++) {
            s[j][0] = __expf(s[j][0] - mn_lo);
            s[j][1] = __expf(s[j][1] - mn_lo);
            s[j][2] = __expf(s[j][2] - mn_hi);
            s[j][3] = __expf(s[j][3] - mn_hi);
            sum_lo += s[j][0] + s[j][1];
            sum_hi += s[j][2] + s[j][3];
        }
#pragma unroll
        for (int off = 1; off <= 2; off <<= 1) {
            sum_lo += __shfl_xor_sync(0xffffffffu, sum_lo, off);
            sum_hi += __shfl_xor_sync(0xffffffffu, sum_hi, off);
        }
        l_lo = l_lo * cor_lo + sum_lo;
        l_hi = l_hi * cor_hi + sum_hi;
#pragma unroll
        for (int j2 = 0; j2 < 8; j2++) {
            o[j2][0] *= cor_lo; o[j2][1] *= cor_lo;
            o[j2][2] *= cor_hi; o[j2][3] *= cor_hi;
        }

        // ---- O += P V ----
        // o[2*jp2 + t] accumulates d-columns jp2*16 + t*8 .. +7  (t = 0,1)
#pragma unroll
        for (int ks2 = 0; ks2 < 8; ks2++) {
            const int j0 = 2 * ks2, j1 = 2 * ks2 + 1;
            uint32_t ph[4], pl[4];
#pragma unroll
            for (int q4 = 0; q4 < 4; q4++) {
                const float p0 = (q4 < 2) ? s[j0][(q4 & 1) * 2]     : s[j1][(q4 & 1) * 2];
                const float p1 = (q4 < 2) ? s[j0][(q4 & 1) * 2 + 1] : s[j1][(q4 & 1) * 2 + 1];
                uint32_t hp = packbf(p0, p1);
                __nv_bfloat162 hb = *(__nv_bfloat162*)&hp;
                float r0 = p0 - __bfloat162float(hb.x);
                float r1 = p1 - __bfloat162float(hb.y);
                ph[q4] = hp;
                pl[q4] = packbf(r0, r1);
            }
#pragma unroll
            for (int jp2 = 0; jp2 < 4; jp2++) {
                uint32_t vh[4], vl[4];
                ldsm4t(vh, Vh_b + (voff + ks2 * 16 * ASTR + jp2 * 16) * 2);
                ldsm4t(vl, Vl_b + (voff + ks2 * 16 * ASTR + jp2 * 16) * 2);
                mma16816(o[2 * jp2],     ph, vh);
                mma16816(o[2 * jp2],     ph, vl);
                mma16816(o[2 * jp2],     pl, vh);
                mma16816(o[2 * jp2 + 1], ph, vh + 2);
                mma16816(o[2 * jp2 + 1], ph, vl + 2);
                mma16816(o[2 * jp2 + 1], pl, vh + 2);
            }
        }
        __syncthreads();   // done reading buf before next-iter cp.async overwrites it
    }

    // ---- epilogue: normalize, split hi/lo, write ctx ----
    const float inv_lo = 1.0f / l_lo;
    const float inv_hi = 1.0f / l_hi;
    const int row_g = qb * 128 + wid * 16 + lr4;
#pragma unroll
    for (int j2 = 0; j2 < 8; j2++) {
        const int col = hoff + j2 * 8 + kq * 2;
        {
            float v0 = o[j2][0] * inv_lo, v1 = o[j2][1] * inv_lo;
            __nv_bfloat16 h0 = __float2bfloat16(v0);
            __nv_bfloat16 h1 = __float2bfloat16(v1);
            __nv_bfloat16 l0 = __float2bfloat16(v0 - __bfloat162float(h0));
            __nv_bfloat16 l1 = __float2bfloat16(v1 - __bfloat162float(h1));
            *(__nv_bfloat162*)&g_ch[(size_t)row_g * DM + col] = __halves2bfloat162(h0, h1);
            *(__nv_bfloat162*)&g_cl[(size_t)row_g * DM + col] = __halves2bfloat162(l0, l1);
        }
        {
            float v0 = o[j2][2] * inv_hi, v1 = o[j2][3] * inv_hi;
            __nv_bfloat16 h0 = __float2bfloat16(v0);
            __nv_bfloat16 h1 = __float2bfloat16(v1);
            __nv_bfloat16 l0 = __float2bfloat16(v0 - __bfloat162float(h0));
            __nv_bfloat16 l1 = __float2bfloat16(v1 - __bfloat162float(h1));
            *(__nv_bfloat162*)&g_ch[(size_t)(row_g + 8) * DM + col] = __halves2bfloat162(h0, h1);
            *(__nv_bfloat162*)&g_cl[(size_t)(row_g + 8) * DM + col] = __halves2bfloat162(l0, l1);
        }
    }
}

// ---------------------------------------------------------------------------
extern "C" void kernel_launch(void* const* d_in, const int* in_sizes, int n_in,
                              void* d_out, int out_size)
{
    const float* x  = (const float*)d_in[0];
    const float* Wq = (const float*)d_in[1];
    const float* Wk = (const float*)d_in[2];
    const float* Wv = (const float*)d_in[3];
    const float* Wo = (const float*)d_in[4];
    const float* bo = (const float*)d_in[5];
    float* out = (float*)d_out;

    cudaFuncSetAttribute(tc_gemm, cudaFuncAttributeMaxDynamicSharedMemorySize, TCG_SMEM);
    cudaFuncSetAttribute(attn_mma, cudaFuncAttributeMaxDynamicSharedMemorySize, ATTN_SMEM);

    const int n2x = SQ * DM / 2;
    const int n2w = DM * DM / 2;

    split_kernel<<<n2x / 256, 256>>>(x,  0, n2x);
    split_kernel<<<n2w / 256, 256>>>(Wq, 1, n2w);
    split_kernel<<<n2w / 256, 256>>>(Wk, 2, n2w);
    split_kernel<<<n2w / 256, 256>>>(Wv, 3, n2w);
    split_kernel<<<n2w / 256, 256>>>(Wo, 4, n2w);

    dim3 gg(DM / 128, SQ / 128);   // (8, 32)
    tc_gemm<<<gg, 256, TCG_SMEM>>>(0, 0, 0, nullptr, nullptr);  // Q (scaled split)
    tc_gemm<<<gg, 256, TCG_SMEM>>>(0, 1, 1, nullptr, nullptr);  // K (split)
    tc_gemm<<<gg, 256, TCG_SMEM>>>(0, 2, 2, nullptr, nullptr);  // V (split)

    attn_mma<<<dim3(SQ / 128, NH), 256, ATTN_SMEM>>>();

    tc_gemm<<<gg, 256, TCG_SMEM>>>(1, 3, 3, out, bo);           // out proj + bias
}

// round 10
// speedup vs baseline: 2.4075x; 1.0815x over previous
#include <cuda_runtime.h>
#include <cuda_bf16.h>
#include <cstdint>

// Problem constants
#define SQ   4096
#define DM   1024
#define NH   16
#define HDIM 64

// ---------------------------------------------------------------------------
// Scratch (allocation-free rule: __device__ globals) — all bf16 hi/lo pairs
// ---------------------------------------------------------------------------
__device__ __align__(16) __nv_bfloat16 g_xh[SQ * DM];
__device__ __align__(16) __nv_bfloat16 g_xl[SQ * DM];
__device__ __align__(16) __nv_bfloat16 g_wh[4][DM * DM];
__device__ __align__(16) __nv_bfloat16 g_wl[4][DM * DM];
__device__ __align__(16) __nv_bfloat16 g_qh[SQ * DM];   // pre-scaled by 0.125
__device__ __align__(16) __nv_bfloat16 g_ql[SQ * DM];
__device__ __align__(16) __nv_bfloat16 g_kh[SQ * DM];
__device__ __align__(16) __nv_bfloat16 g_kl[SQ * DM];
__device__ __align__(16) __nv_bfloat16 g_vh[SQ * DM];
__device__ __align__(16) __nv_bfloat16 g_vl[SQ * DM];
__device__ __align__(16) __nv_bfloat16 g_ch[SQ * DM];
__device__ __align__(16) __nv_bfloat16 g_cl[SQ * DM];

// ---------------------------------------------------------------------------
// PTX helpers (legacy / non-'a' instructions only: HMMA, ldmatrix, cp.async)
// ---------------------------------------------------------------------------
__device__ __forceinline__ uint32_t smem_to_u32(const void* p) {
    uint32_t a;
    asm("{ .reg .u64 t; cvta.to.shared.u64 t, %1; cvt.u32.u64 %0, t; }"
        : "=r"(a) : "l"(p));
    return a;
}

__device__ __forceinline__ void mma16816(float* c, const uint32_t* a, const uint32_t* b)
{
    asm volatile(
        "mma.sync.aligned.m16n8k16.row.col.f32.bf16.bf16.f32 "
        "{%0,%1,%2,%3}, {%4,%5,%6,%7}, {%8,%9}, {%0,%1,%2,%3};\n"
        : "+f"(c[0]), "+f"(c[1]), "+f"(c[2]), "+f"(c[3])
        : "r"(a[0]), "r"(a[1]), "r"(a[2]), "r"(a[3]), "r"(b[0]), "r"(b[1]));
}

__device__ __forceinline__ void ldsm4(uint32_t* r, uint32_t addr)
{
    asm volatile("ldmatrix.sync.aligned.m8n8.x4.shared.b16 {%0,%1,%2,%3}, [%4];"
        : "=r"(r[0]), "=r"(r[1]), "=r"(r[2]), "=r"(r[3]) : "r"(addr));
}

__device__ __forceinline__ void ldsm4t(uint32_t* r, uint32_t addr)
{
    asm volatile("ldmatrix.sync.aligned.m8n8.x4.trans.shared.b16 {%0,%1,%2,%3}, [%4];"
        : "=r"(r[0]), "=r"(r[1]), "=r"(r[2]), "=r"(r[3]) : "r"(addr));
}

__device__ __forceinline__ void cp16(uint32_t dst, const void* src)
{
    asm volatile("cp.async.ca.shared.global [%0], [%1], 16;" :: "r"(dst), "l"(src));
}
#define CP_COMMIT() asm volatile("cp.async.commit_group;" ::: "memory")
#define CP_WAIT0()  asm volatile("cp.async.wait_group 0;" ::: "memory")
#define CP_WAIT1()  asm volatile("cp.async.wait_group 1;" ::: "memory")
#define CP_WAIT2()  asm volatile("cp.async.wait_group 2;" ::: "memory")

__device__ __forceinline__ uint32_t packbf(float lo, float hi)
{
    uint32_t r;
    asm("cvt.rn.bf16x2.f32 %0, %1, %2;" : "=r"(r) : "f"(hi), "f"(lo));
    return r;
}

// ---------------------------------------------------------------------------
// fp32 -> bf16 hi/lo splitters
// ---------------------------------------------------------------------------
__device__ __forceinline__ void split_pair(const float2 v, __nv_bfloat16* hi,
                                           __nv_bfloat16* lo, int i)
{
    __nv_bfloat16 h0 = __float2bfloat16(v.x);
    __nv_bfloat16 h1 = __float2bfloat16(v.y);
    __nv_bfloat16 l0 = __float2bfloat16(v.x - __bfloat162float(h0));
    __nv_bfloat16 l1 = __float2bfloat16(v.y - __bfloat162float(h1));
    ((__nv_bfloat162*)hi)[i] = __halves2bfloat162(h0, h1);
    ((__nv_bfloat162*)lo)[i] = __halves2bfloat162(l0, l1);
}

__global__ void split_x(const float* __restrict__ src, int n2)
{
    int i = blockIdx.x * blockDim.x + threadIdx.x;
    if (i >= n2) return;
    split_pair(((const float2*)src)[i], g_xh, g_xl, i);
}

// all four weights in one launch: blockIdx.y = weight index
__global__ void split_w(const float* __restrict__ w0, const float* __restrict__ w1,
                        const float* __restrict__ w2, const float* __restrict__ w3,
                        int n2)
{
    int wi = blockIdx.y;
    const float* src = (wi == 0) ? w0 : (wi == 1) ? w1 : (wi == 2) ? w2 : w3;
    int i = blockIdx.x * blockDim.x + threadIdx.x;
    if (i >= n2) return;
    split_pair(((const float2*)src)[i], g_wh[wi], g_wl[wi], i);
}

// ---------------------------------------------------------------------------
// HMMA GEMM: C[4096,1024] = A[4096,1024] * B[1024,1024]^T
// gridDim.z==3: z selects wsel=csel=z (QKV fused, asel=0).
// csel 0: -> (g_qh,g_ql) scaled 0.125 | 1: (g_kh,g_kl) | 2: (g_vh,g_vl)
// csel 3: fp32 + bias -> Cparam
// BK=16, 3-stage cp.async pipeline, ldmatrix fragment loads.
// Stage layout: 4 arrays (Ah,Al,Bh,Bl) of [128][24] bf16 (48B rows).
// ---------------------------------------------------------------------------
#define GSTR 24
#define GARR (128 * GSTR)              // 3072 bf16 = 6144 B
#define NSTG 3
#define TCG_SMEM (int)(NSTG * 4 * GARR * sizeof(__nv_bfloat16))   // 73728 B

__global__ __launch_bounds__(256, 1)
void tc_gemm(int asel, int wsel, int csel, float* Cparam, const float* bias)
{
    extern __shared__ __nv_bfloat16 smem[];
    const uint32_t sbase = smem_to_u32(smem);

    if (gridDim.z == 3) { wsel = blockIdx.z; csel = blockIdx.z; }

    const __nv_bfloat16* GAh = asel ? g_ch : g_xh;
    const __nv_bfloat16* GAl = asel ? g_cl : g_xl;
    const __nv_bfloat16* GBh = g_wh[wsel];
    const __nv_bfloat16* GBl = g_wl[wsel];

    const int tid  = threadIdx.x;
    const int wid  = tid >> 5;
    const int lane = tid & 31;
    const int wm   = wid >> 2;        // 0..1
    const int wn   = wid & 3;         // 0..3
    const int lr4  = lane >> 2;
    const int kq   = lane & 3;
    const int m0   = blockIdx.y * 128;
    const int n0   = blockIdx.x * 128;

    // loader mapping: 128 rows x 2 k-chunks of 8 bf16
    const int row = tid >> 1;
    const int kc  = tid & 1;
    const size_t gA = (size_t)(m0 + row) * DM + kc * 8;
    const size_t gB = (size_t)(n0 + row) * DM + kc * 8;
    const uint32_t so = (uint32_t)(row * GSTR + kc * 8) * 2;   // byte offset in array

    // ldmatrix lane address offsets (bytes, within one array)
    const uint32_t aoff = (uint32_t)((wm * 64 + (lane & 15)) * GSTR + ((lane >> 4) & 1) * 8) * 2;
    const uint32_t boff = (uint32_t)((wn * 32 + (lane & 7) + ((lane >> 4) & 1) * 8) * GSTR
                                     + ((lane >> 3) & 1) * 8) * 2;

    float c[4][4][4];
#pragma unroll
    for (int i = 0; i < 4; i++)
#pragma unroll
        for (int j = 0; j < 4; j++)
#pragma unroll
            for (int e = 0; e < 4; e++) c[i][j][e] = 0.f;

#define ISSUE_STAGE(t) do { \
        uint32_t sb_ = sbase + (uint32_t)(((t) % NSTG) * 4 * GARR) * 2; \
        size_t ko_ = (size_t)(t) * 16; \
        cp16(sb_ + so,                GAh + gA + ko_); \
        cp16(sb_ + GARR * 2 + so,     GAl + gA + ko_); \
        cp16(sb_ + 2 * GARR * 2 + so, GBh + gB + ko_); \
        cp16(sb_ + 3 * GARR * 2 + so, GBl + gB + ko_); \
        CP_COMMIT(); \
    } while (0)

    ISSUE_STAGE(0);
    ISSUE_STAGE(1);
    ISSUE_STAGE(2);

    for (int t = 0; t < 64; t++) {
        if (t < 62) CP_WAIT2();
        else if (t == 62) CP_WAIT1();
        else CP_WAIT0();
        __syncthreads();

        const uint32_t stg = sbase + (uint32_t)((t % NSTG) * 4 * GARR) * 2;

        uint32_t ah[4][4], al[4][4], bh[2][4], bl[2][4];
#pragma unroll
        for (int i = 0; i < 4; i++) {
            ldsm4(ah[i], stg + aoff + (uint32_t)(i * 16 * GSTR) * 2);
            ldsm4(al[i], stg + GARR * 2 + aoff + (uint32_t)(i * 16 * GSTR) * 2);
        }
#pragma unroll
        for (int jj = 0; jj < 2; jj++) {
            ldsm4(bh[jj], stg + 2 * GARR * 2 + boff + (uint32_t)(jj * 16 * GSTR) * 2);
            ldsm4(bl[jj], stg + 3 * GARR * 2 + boff + (uint32_t)(jj * 16 * GSTR) * 2);
        }

#pragma unroll
        for (int i = 0; i < 4; i++)
#pragma unroll
            for (int j = 0; j < 4; j++) {
                const uint32_t* fh = bh[j >> 1] + (j & 1) * 2;
                const uint32_t* fl = bl[j >> 1] + (j & 1) * 2;
                mma16816(c[i][j], ah[i], fh);
                mma16816(c[i][j], ah[i], fl);
                mma16816(c[i][j], al[i], fh);
            }

        if (t + 3 < 64) {
            __syncthreads();          // all warps done reading slot before refill
            ISSUE_STAGE(t + 3);
        }
    }
#undef ISSUE_STAGE

    if (csel < 3) {
        __nv_bfloat16* Hd = (csel == 0) ? g_qh : (csel == 1) ? g_kh : g_vh;
        __nv_bfloat16* Ld = (csel == 0) ? g_ql : (csel == 1) ? g_kl : g_vl;
        const float scale = (csel == 0) ? 0.125f : 1.0f;
#pragma unroll
        for (int i = 0; i < 4; i++) {
            int r = m0 + wm * 64 + i * 16 + lr4;
#pragma unroll
            for (int j = 0; j < 4; j++) {
                int col = n0 + wn * 32 + j * 8 + kq * 2;
#pragma unroll
                for (int half = 0; half < 2; half++) {
                    int rr = r + half * 8;
                    float v0 = c[i][j][half * 2 + 0] * scale;
                    float v1 = c[i][j][half * 2 + 1] * scale;
                    __nv_bfloat16 h0 = __float2bfloat16(v0);
                    __nv_bfloat16 h1 = __float2bfloat16(v1);
                    __nv_bfloat16 l0 = __float2bfloat16(v0 - __bfloat162float(h0));
                    __nv_bfloat16 l1 = __float2bfloat16(v1 - __bfloat162float(h1));
                    *(__nv_bfloat162*)&Hd[(size_t)rr * DM + col] = __halves2bfloat162(h0, h1);
                    *(__nv_bfloat162*)&Ld[(size_t)rr * DM + col] = __halves2bfloat162(l0, l1);
                }
            }
        }
    } else {
#pragma unroll
        for (int i = 0; i < 4; i++) {
            int r = m0 + wm * 64 + i * 16 + lr4;
#pragma unroll
            for (int j = 0; j < 4; j++) {
                int col = n0 + wn * 32 + j * 8 + kq * 2;
                float bx = bias[col], by = bias[col + 1];
                *(float2*)(Cparam + (size_t)r * DM + col)       = make_float2(c[i][j][0] + bx, c[i][j][1] + by);
                *(float2*)(Cparam + (size_t)(r + 8) * DM + col) = make_float2(c[i][j][2] + bx, c[i][j][3] + by);
            }
        }
    }
}

// ---------------------------------------------------------------------------
// MMA flash attention, causal (unchanged from R8 passing version).
// ---------------------------------------------------------------------------
#define ASTR 72
#define ATILE (128 * ASTR)              // 9216 bf16
#define ATTN_SMEM (int)((2 * ATILE + 2 * 4 * ATILE) * sizeof(__nv_bfloat16))  // 184320 B

__device__ __forceinline__ void kv_load(uint32_t sbase, int tid, int kb, int buf, int hoff)
{
#pragma unroll
    for (int i = 0; i < 16; i++) {
        int id  = tid + 256 * i;
        int arr = id >> 10;
        int rem = id & 1023;
        int row = rem >> 3;
        int ch  = rem & 7;
        const __nv_bfloat16* src =
            ((arr == 0) ? g_kh : (arr == 1) ? g_kl : (arr == 2) ? g_vh : g_vl)
            + (size_t)(kb * 128 + row) * DM + hoff + ch * 8;
        uint32_t dst = sbase + (uint32_t)(18432 + buf * 36864 + arr * 9216 + row * ASTR + ch * 8) * 2;
        cp16(dst, src);
    }
}

__global__ __launch_bounds__(256, 1)
void attn_mma()
{
    extern __shared__ __nv_bfloat16 asm_sm[];
    const uint32_t sbase = smem_to_u32(asm_sm);

    const int qb   = gridDim.x - 1 - blockIdx.x;    // reversed: long CTAs first
    const int h    = blockIdx.y;
    const int hoff = h * HDIM;
    const int tid  = threadIdx.x;
    const int wid  = tid >> 5;
    const int lane = tid & 31;
    const int lr4  = lane >> 2;
    const int kq   = lane & 3;

    // Q load (cp.async)
#pragma unroll
    for (int i = 0; i < 8; i++) {
        int id  = tid + 256 * i;
        int arr = id >> 10;
        int rem = id & 1023;
        int row = rem >> 3;
        int ch  = rem & 7;
        const __nv_bfloat16* src = (arr ? g_ql : g_qh)
            + (size_t)(qb * 128 + row) * DM + hoff + ch * 8;
        uint32_t dst = sbase + (uint32_t)(arr * 9216 + row * ASTR + ch * 8) * 2;
        cp16(dst, src);
    }
    kv_load(sbase, tid, 0, 0, hoff);
    CP_COMMIT();

    const uint32_t qoff = (uint32_t)((wid * 16 + (lane & 7) + ((lane >> 3) & 1) * 8) * ASTR
                                     + ((lane >> 4) & 1) * 8);
    const uint32_t koff = (uint32_t)(((lane & 7) + ((lane >> 4) & 1) * 8) * ASTR
                                     + ((lane >> 3) & 1) * 8);
    const uint32_t voff = (uint32_t)(((lane & 7) + ((lane >> 3) & 1) * 8) * ASTR
                                     + ((lane >> 4) & 1) * 8);

    float o[8][4];
#pragma unroll
    for (int i = 0; i < 8; i++)
#pragma unroll
        for (int e = 0; e < 4; e++) o[i][e] = 0.f;
    float m_lo = -1e30f, m_hi = -1e30f, l_lo = 0.f, l_hi = 0.f;

    for (int kb = 0; kb <= qb; kb++) {
        const int buf = kb & 1;
        if (kb < qb) {
            kv_load(sbase, tid, kb + 1, buf ^ 1, hoff);
            CP_COMMIT();
            CP_WAIT1();
        } else {
            CP_WAIT0();
        }
        __syncthreads();

        const uint32_t Qh_b = sbase;
        const uint32_t Ql_b = sbase + 9216 * 2;
        const uint32_t Kh_b = sbase + (uint32_t)(18432 + buf * 36864) * 2;
        const uint32_t Kl_b = Kh_b + 9216 * 2;
        const uint32_t Vh_b = Kh_b + 2 * 9216 * 2;
        const uint32_t Vl_b = Kh_b + 3 * 9216 * 2;

        // ---- S = Q K^T ----
        float s[16][4];
#pragma unroll
        for (int j = 0; j < 16; j++)
#pragma unroll
            for (int e = 0; e < 4; e++) s[j][e] = 0.f;

#pragma unroll
        for (int ks = 0; ks < 4; ks++) {
            uint32_t ah[4], al[4];
            ldsm4(ah, Qh_b + (qoff + ks * 16) * 2);
            ldsm4(al, Ql_b + (qoff + ks * 16) * 2);
#pragma unroll
            for (int jp = 0; jp < 8; jp++) {
                uint32_t bh[4], bl[4];
                ldsm4(bh, Kh_b + (koff + jp * 16 * ASTR + ks * 16) * 2);
                ldsm4(bl, Kl_b + (koff + jp * 16 * ASTR + ks * 16) * 2);
                mma16816(s[2 * jp],     ah, bh);
                mma16816(s[2 * jp],     ah, bl);
                mma16816(s[2 * jp],     al, bh);
                mma16816(s[2 * jp + 1], ah, bh + 2);
                mma16816(s[2 * jp + 1], ah, bl + 2);
                mma16816(s[2 * jp + 1], al, bh + 2);
            }
        }

        // ---- causal mask (diag block only) ----
        if (kb == qb) {
            const int rl = wid * 16 + lr4;
#pragma unroll
            for (int j = 0; j < 16; j++) {
                int c0 = j * 8 + kq * 2;
                if (c0     > rl)     s[j][0] = -1e30f;
                if (c0 + 1 > rl)     s[j][1] = -1e30f;
                if (c0     > rl + 8) s[j][2] = -1e30f;
                if (c0 + 1 > rl + 8) s[j][3] = -1e30f;
            }
        }

        // ---- online softmax ----
        float bm_lo = -1e30f, bm_hi = -1e30f;
#pragma unroll
        for (int j = 0; j < 16; j++) {
            bm_lo = fmaxf(bm_lo, fmaxf(s[j][0], s[j][1]));
            bm_hi = fmaxf(bm_hi, fmaxf(s[j][2], s[j][3]));
        }
#pragma unroll
        for (int off = 1; off <= 2; off <<= 1) {
            bm_lo = fmaxf(bm_lo, __shfl_xor_sync(0xffffffffu, bm_lo, off));
            bm_hi = fmaxf(bm_hi, __shfl_xor_sync(0xffffffffu, bm_hi, off));
        }
        const float mn_lo = fmaxf(m_lo, bm_lo);
        const float mn_hi = fmaxf(m_hi, bm_hi);
        const float cor_lo = __expf(m_lo - mn_lo);
        const float cor_hi = __expf(m_hi - mn_hi);
        m_lo = mn_lo; m_hi = mn_hi;

        float sum_lo = 0.f, sum_hi = 0.f;
#pragma unroll
        for (int j = 0; j < 16; j++) {
            s[j][0] = __expf(s[j][0] - mn_lo);
            s[j][1] = __expf(s[j][1] - mn_lo);
            s[j][2] = __expf(s[j][2] - mn_hi);
            s[j][3] = __expf(s[j][3] - mn_hi);
            sum_lo += s[j][0] + s[j][1];
            sum_hi += s[j][2] + s[j][3];
        }
#pragma unroll
        for (int off = 1; off <= 2; off <<= 1) {
            sum_lo += __shfl_xor_sync(0xffffffffu, sum_lo, off);
            sum_hi += __shfl_xor_sync(0xffffffffu, sum_hi, off);
        }
        l_lo = l_lo * cor_lo + sum_lo;
        l_hi = l_hi * cor_hi + sum_hi;
#pragma unroll
        for (int j2 = 0; j2 < 8; j2++) {
            o[j2][0] *= cor_lo; o[j2][1] *= cor_lo;
            o[j2][2] *= cor_hi; o[j2][3] *= cor_hi;
        }

        // ---- O += P V ----
#pragma unroll
        for (int ks2 = 0; ks2 < 8; ks2++) {
            const int j0 = 2 * ks2, j1 = 2 * ks2 + 1;
            uint32_t ph[4], pl[4];
#pragma unroll
            for (int q4 = 0; q4 < 4; q4++) {
                const float p0 = (q4 < 2) ? s[j0][(q4 & 1) * 2]     : s[j1][(q4 & 1) * 2];
                const float p1 = (q4 < 2) ? s[j0][(q4 & 1) * 2 + 1] : s[j1][(q4 & 1) * 2 + 1];
                uint32_t hp = packbf(p0, p1);
                __nv_bfloat162 hb = *(__nv_bfloat162*)&hp;
                float r0 = p0 - __bfloat162float(hb.x);
                float r1 = p1 - __bfloat162float(hb.y);
                ph[q4] = hp;
                pl[q4] = packbf(r0, r1);
            }
#pragma unroll
            for (int jp2 = 0; jp2 < 4; jp2++) {
                uint32_t vh[4], vl[4];
                ldsm4t(vh, Vh_b + (voff + ks2 * 16 * ASTR + jp2 * 16) * 2);
                ldsm4t(vl, Vl_b + (voff + ks2 * 16 * ASTR + jp2 * 16) * 2);
                mma16816(o[2 * jp2],     ph, vh);
                mma16816(o[2 * jp2],     ph, vl);
                mma16816(o[2 * jp2],     pl, vh);
                mma16816(o[2 * jp2 + 1], ph, vh + 2);
                mma16816(o[2 * jp2 + 1], ph, vl + 2);
                mma16816(o[2 * jp2 + 1], pl, vh + 2);
            }
        }
        __syncthreads();
    }

    // ---- epilogue ----
    const float inv_lo = 1.0f / l_lo;
    const float inv_hi = 1.0f / l_hi;
    const int row_g = qb * 128 + wid * 16 + lr4;
#pragma unroll
    for (int j2 = 0; j2 < 8; j2++) {
        const int col = hoff + j2 * 8 + kq * 2;
        {
            float v0 = o[j2][0] * inv_lo, v1 = o[j2][1] * inv_lo;
            __nv_bfloat16 h0 = __float2bfloat16(v0);
            __nv_bfloat16 h1 = __float2bfloat16(v1);
            __nv_bfloat16 l0 = __float2bfloat16(v0 - __bfloat162float(h0));
            __nv_bfloat16 l1 = __float2bfloat16(v1 - __bfloat162float(h1));
            *(__nv_bfloat162*)&g_ch[(size_t)row_g * DM + col] = __halves2bfloat162(h0, h1);
            *(__nv_bfloat162*)&g_cl[(size_t)row_g * DM + col] = __halves2bfloat162(l0, l1);
        }
        {
            float v0 = o[j2][2] * inv_hi, v1 = o[j2][3] * inv_hi;
            __nv_bfloat16 h0 = __float2bfloat16(v0);
            __nv_bfloat16 h1 = __float2bfloat16(v1);
            __nv_bfloat16 l0 = __float2bfloat16(v0 - __bfloat162float(h0));
            __nv_bfloat16 l1 = __float2bfloat16(v1 - __bfloat162float(h1));
            *(__nv_bfloat162*)&g_ch[(size_t)(row_g + 8) * DM + col] = __halves2bfloat162(h0, h1);
            *(__nv_bfloat162*)&g_cl[(size_t)(row_g + 8) * DM + col] = __halves2bfloat162(l0, l1);
        }
    }
}

// ---------------------------------------------------------------------------
extern "C" void kernel_launch(void* const* d_in, const int* in_sizes, int n_in,
                              void* d_out, int out_size)
{
    const float* x  = (const float*)d_in[0];
    const float* Wq = (const float*)d_in[1];
    const float* Wk = (const float*)d_in[2];
    const float* Wv = (const float*)d_in[3];
    const float* Wo = (const float*)d_in[4];
    const float* bo = (const float*)d_in[5];
    float* out = (float*)d_out;

    cudaFuncSetAttribute(tc_gemm, cudaFuncAttributeMaxDynamicSharedMemorySize, TCG_SMEM);
    cudaFuncSetAttribute(attn_mma, cudaFuncAttributeMaxDynamicSharedMemorySize, ATTN_SMEM);

    const int n2x = SQ * DM / 2;
    const int n2w = DM * DM / 2;

    split_x<<<n2x / 256, 256>>>(x, n2x);
    split_w<<<dim3(n2w / 256, 4), 256>>>(Wq, Wk, Wv, Wo, n2w);

    tc_gemm<<<dim3(DM / 128, SQ / 128, 3), 256, TCG_SMEM>>>(0, 0, 0, nullptr, nullptr);  // QKV

    attn_mma<<<dim3(SQ / 128, NH), 256, ATTN_SMEM>>>();

    tc_gemm<<<dim3(DM / 128, SQ / 128, 1), 256, TCG_SMEM>>>(1, 3, 3, out, bo);           // out proj
}

// round 11
// speedup vs baseline: 2.8556x; 1.1861x over previous
#include <cuda_runtime.h>
#include <cuda_bf16.h>
#include <cstdint>

// Problem constants
#define SQ   4096
#define DM   1024
#define NH   16
#define HDIM 64

// ---------------------------------------------------------------------------
// Scratch (allocation-free rule: __device__ globals) — all bf16 hi/lo pairs
// ---------------------------------------------------------------------------
__device__ __align__(16) __nv_bfloat16 g_xh[SQ * DM];
__device__ __align__(16) __nv_bfloat16 g_xl[SQ * DM];
__device__ __align__(16) __nv_bfloat16 g_wh[4][DM * DM];
__device__ __align__(16) __nv_bfloat16 g_wl[4][DM * DM];
__device__ __align__(16) __nv_bfloat16 g_qh[SQ * DM];   // pre-scaled by 0.125
__device__ __align__(16) __nv_bfloat16 g_ql[SQ * DM];
__device__ __align__(16) __nv_bfloat16 g_kh[SQ * DM];
__device__ __align__(16) __nv_bfloat16 g_kl[SQ * DM];
__device__ __align__(16) __nv_bfloat16 g_vh[SQ * DM];
__device__ __align__(16) __nv_bfloat16 g_vl[SQ * DM];
__device__ __align__(16) __nv_bfloat16 g_ch[SQ * DM];
__device__ __align__(16) __nv_bfloat16 g_cl[SQ * DM];

// ---------------------------------------------------------------------------
// PTX helpers (legacy / non-'a' instructions only: HMMA, ldmatrix, cp.async)
// ---------------------------------------------------------------------------
__device__ __forceinline__ uint32_t smem_to_u32(const void* p) {
    uint32_t a;
    asm("{ .reg .u64 t; cvta.to.shared.u64 t, %1; cvt.u32.u64 %0, t; }"
        : "=r"(a) : "l"(p));
    return a;
}

__device__ __forceinline__ void mma16816(float* c, const uint32_t* a, const uint32_t* b)
{
    asm volatile(
        "mma.sync.aligned.m16n8k16.row.col.f32.bf16.bf16.f32 "
        "{%0,%1,%2,%3}, {%4,%5,%6,%7}, {%8,%9}, {%0,%1,%2,%3};\n"
        : "+f"(c[0]), "+f"(c[1]), "+f"(c[2]), "+f"(c[3])
        : "r"(a[0]), "r"(a[1]), "r"(a[2]), "r"(a[3]), "r"(b[0]), "r"(b[1]));
}

__device__ __forceinline__ void ldsm4(uint32_t* r, uint32_t addr)
{
    asm volatile("ldmatrix.sync.aligned.m8n8.x4.shared.b16 {%0,%1,%2,%3}, [%4];"
        : "=r"(r[0]), "=r"(r[1]), "=r"(r[2]), "=r"(r[3]) : "r"(addr));
}

__device__ __forceinline__ void ldsm4t(uint32_t* r, uint32_t addr)
{
    asm volatile("ldmatrix.sync.aligned.m8n8.x4.trans.shared.b16 {%0,%1,%2,%3}, [%4];"
        : "=r"(r[0]), "=r"(r[1]), "=r"(r[2]), "=r"(r[3]) : "r"(addr));
}

__device__ __forceinline__ void cp16(uint32_t dst, const void* src)
{
    asm volatile("cp.async.ca.shared.global [%0], [%1], 16;" :: "r"(dst), "l"(src));
}
#define CP_COMMIT() asm volatile("cp.async.commit_group;" ::: "memory")
#define CP_WAIT0()  asm volatile("cp.async.wait_group 0;" ::: "memory")
#define CP_WAIT1()  asm volatile("cp.async.wait_group 1;" ::: "memory")
#define CP_WAIT2()  asm volatile("cp.async.wait_group 2;" ::: "memory")

__device__ __forceinline__ uint32_t packbf(float lo, float hi)
{
    uint32_t r;
    asm("cvt.rn.bf16x2.f32 %0, %1, %2;" : "=r"(r) : "f"(hi), "f"(lo));
    return r;
}

// ---------------------------------------------------------------------------
// fp32 -> bf16 hi/lo splitters
// ---------------------------------------------------------------------------
__device__ __forceinline__ void split_pair(const float2 v, __nv_bfloat16* hi,
                                           __nv_bfloat16* lo, int i)
{
    __nv_bfloat16 h0 = __float2bfloat16(v.x);
    __nv_bfloat16 h1 = __float2bfloat16(v.y);
    __nv_bfloat16 l0 = __float2bfloat16(v.x - __bfloat162float(h0));
    __nv_bfloat16 l1 = __float2bfloat16(v.y - __bfloat162float(h1));
    ((__nv_bfloat162*)hi)[i] = __halves2bfloat162(h0, h1);
    ((__nv_bfloat162*)lo)[i] = __halves2bfloat162(l0, l1);
}

__global__ void split_x(const float* __restrict__ src, int n2)
{
    int i = blockIdx.x * blockDim.x + threadIdx.x;
    if (i >= n2) return;
    split_pair(((const float2*)src)[i], g_xh, g_xl, i);
}

// all four weights in one launch: blockIdx.y = weight index
__global__ void split_w(const float* __restrict__ w0, const float* __restrict__ w1,
                        const float* __restrict__ w2, const float* __restrict__ w3,
                        int n2)
{
    int wi = blockIdx.y;
    const float* src = (wi == 0) ? w0 : (wi == 1) ? w1 : (wi == 2) ? w2 : w3;
    int i = blockIdx.x * blockDim.x + threadIdx.x;
    if (i >= n2) return;
    split_pair(((const float2*)src)[i], g_wh[wi], g_wl[wi], i);
}

// ---------------------------------------------------------------------------
// HMMA GEMM: C[4096,1024] = A[4096,1024] * B[1024,1024]^T
// gridDim.z==3: z selects wsel=csel=z (QKV fused, asel=0).
// csel 0: -> (g_qh,g_ql) scaled 0.125 | 1: (g_kh,g_kl) | 2: (g_vh,g_vl)
// csel 3: fp32 + bias -> Cparam
// BK=32 per iteration (2 k16 halves), 4-stage cp.async pipeline,
// ONE __syncthreads per iteration (issue into slot (t-1)%4 post-barrier).
// Stage layout: 4 arrays (Ah,Al,Bh,Bl) of [128][40] bf16 (80B rows, data 64B).
// ---------------------------------------------------------------------------
#define GSTR 40
#define GARR (128 * GSTR)              // 5120 bf16 = 10240 B
#define NSTG 4
#define TCG_SMEM (int)(NSTG * 4 * GARR * sizeof(__nv_bfloat16))   // 163840 B

__global__ __launch_bounds__(256, 1)
void tc_gemm(int asel, int wsel, int csel, float* Cparam, const float* bias)
{
    extern __shared__ __nv_bfloat16 smem[];
    const uint32_t sbase = smem_to_u32(smem);

    if (gridDim.z == 3) { wsel = blockIdx.z; csel = blockIdx.z; }

    const __nv_bfloat16* GAh = asel ? g_ch : g_xh;
    const __nv_bfloat16* GAl = asel ? g_cl : g_xl;
    const __nv_bfloat16* GBh = g_wh[wsel];
    const __nv_bfloat16* GBl = g_wl[wsel];

    const int tid  = threadIdx.x;
    const int wid  = tid >> 5;
    const int lane = tid & 31;
    const int wm   = wid >> 2;        // 0..1
    const int wn   = wid & 3;         // 0..3
    const int lr4  = lane >> 2;
    const int kq   = lane & 3;
    const int m0   = blockIdx.y * 128;
    const int n0   = blockIdx.x * 128;

    // loader mapping: per array, 512 chunks of 16B; thread does 2 (k=0,1):
    //   c = tid + 256k, row = c>>2 (0..127), ch = c&3 (16B chunk in 64B row)
    const int lrow0 = tid >> 2;            // rows for k=0: 0..63
    const int lch   = tid & 3;
    // per-thread byte offsets within one array (k=0 and k=1 rows differ by 64)
    const uint32_t sd0 = (uint32_t)(lrow0 * GSTR + lch * 8) * 2;
    const uint32_t sd1 = (uint32_t)((lrow0 + 64) * GSTR + lch * 8) * 2;

    // ldmatrix lane address offsets (bytes, within one array, k-half 0)
    const uint32_t aoff = (uint32_t)((wm * 64 + (lane & 15)) * GSTR + ((lane >> 4) & 1) * 8) * 2;
    const uint32_t boff = (uint32_t)((wn * 32 + (lane & 7) + ((lane >> 4) & 1) * 8) * GSTR
                                     + ((lane >> 3) & 1) * 8) * 2;

    float c[4][4][4];
#pragma unroll
    for (int i = 0; i < 4; i++)
#pragma unroll
        for (int j = 0; j < 4; j++)
#pragma unroll
            for (int e = 0; e < 4; e++) c[i][j][e] = 0.f;

#define ISSUE_STAGE(t) do { \
        uint32_t sb_ = sbase + (uint32_t)(((t) % NSTG) * 4 * GARR) * 2; \
        size_t koA0_ = (size_t)(m0 + lrow0) * DM + (size_t)(t) * 32 + lch * 8; \
        size_t koA1_ = (size_t)(m0 + lrow0 + 64) * DM + (size_t)(t) * 32 + lch * 8; \
        size_t koB0_ = (size_t)(n0 + lrow0) * DM + (size_t)(t) * 32 + lch * 8; \
        size_t koB1_ = (size_t)(n0 + lrow0 + 64) * DM + (size_t)(t) * 32 + lch * 8; \
        cp16(sb_ + sd0,                GAh + koA0_); \
        cp16(sb_ + sd1,                GAh + koA1_); \
        cp16(sb_ + GARR * 2 + sd0,     GAl + koA0_); \
        cp16(sb_ + GARR * 2 + sd1,     GAl + koA1_); \
        cp16(sb_ + 2 * GARR * 2 + sd0, GBh + koB0_); \
        cp16(sb_ + 2 * GARR * 2 + sd1, GBh + koB1_); \
        cp16(sb_ + 3 * GARR * 2 + sd0, GBl + koB0_); \
        cp16(sb_ + 3 * GARR * 2 + sd1, GBl + koB1_); \
        CP_COMMIT(); \
    } while (0)

    ISSUE_STAGE(0);
    ISSUE_STAGE(1);
    ISSUE_STAGE(2);

    for (int t = 0; t < 32; t++) {
        if (t < 30) CP_WAIT2();
        else if (t == 30) CP_WAIT1();
        else CP_WAIT0();
        __syncthreads();
        // refill slot (t+3)%4 == (t-1)%4: all warps finished its reads at iter t-1
        if (t + 3 < 32) ISSUE_STAGE(t + 3);

        const uint32_t stg = sbase + (uint32_t)((t % NSTG) * 4 * GARR) * 2;

#pragma unroll
        for (int kh = 0; kh < 2; kh++) {
            const uint32_t ko = (uint32_t)(kh * 16) * 2;   // +16 bf16 per k-half
            uint32_t ah[4][4], al[4][4], bh[2][4], bl[2][4];
#pragma unroll
            for (int i = 0; i < 4; i++) {
                ldsm4(ah[i], stg + aoff + ko + (uint32_t)(i * 16 * GSTR) * 2);
                ldsm4(al[i], stg + GARR * 2 + aoff + ko + (uint32_t)(i * 16 * GSTR) * 2);
            }
#pragma unroll
            for (int jj = 0; jj < 2; jj++) {
                ldsm4(bh[jj], stg + 2 * GARR * 2 + boff + ko + (uint32_t)(jj * 16 * GSTR) * 2);
                ldsm4(bl[jj], stg + 3 * GARR * 2 + boff + ko + (uint32_t)(jj * 16 * GSTR) * 2);
            }

#pragma unroll
            for (int i = 0; i < 4; i++)
#pragma unroll
                for (int j = 0; j < 4; j++) {
                    const uint32_t* fh = bh[j >> 1] + (j & 1) * 2;
                    const uint32_t* fl = bl[j >> 1] + (j & 1) * 2;
                    mma16816(c[i][j], ah[i], fh);
                    mma16816(c[i][j], ah[i], fl);
                    mma16816(c[i][j], al[i], fh);
                }
        }
    }
#undef ISSUE_STAGE

    if (csel < 3) {
        __nv_bfloat16* Hd = (csel == 0) ? g_qh : (csel == 1) ? g_kh : g_vh;
        __nv_bfloat16* Ld = (csel == 0) ? g_ql : (csel == 1) ? g_kl : g_vl;
        const float scale = (csel == 0) ? 0.125f : 1.0f;
#pragma unroll
        for (int i = 0; i < 4; i++) {
            int r = m0 + wm * 64 + i * 16 + lr4;
#pragma unroll
            for (int j = 0; j < 4; j++) {
                int col = n0 + wn * 32 + j * 8 + kq * 2;
#pragma unroll
                for (int half = 0; half < 2; half++) {
                    int rr = r + half * 8;
                    float v0 = c[i][j][half * 2 + 0] * scale;
                    float v1 = c[i][j][half * 2 + 1] * scale;
                    __nv_bfloat16 h0 = __float2bfloat16(v0);
                    __nv_bfloat16 h1 = __float2bfloat16(v1);
                    __nv_bfloat16 l0 = __float2bfloat16(v0 - __bfloat162float(h0));
                    __nv_bfloat16 l1 = __float2bfloat16(v1 - __bfloat162float(h1));
                    *(__nv_bfloat162*)&Hd[(size_t)rr * DM + col] = __halves2bfloat162(h0, h1);
                    *(__nv_bfloat162*)&Ld[(size_t)rr * DM + col] = __halves2bfloat162(l0, l1);
                }
            }
        }
    } else {
#pragma unroll
        for (int i = 0; i < 4; i++) {
            int r = m0 + wm * 64 + i * 16 + lr4;
#pragma unroll
            for (int j = 0; j < 4; j++) {
                int col = n0 + wn * 32 + j * 8 + kq * 2;
                float bx = bias[col], by = bias[col + 1];
                *(float2*)(Cparam + (size_t)r * DM + col)       = make_float2(c[i][j][0] + bx, c[i][j][1] + by);
                *(float2*)(Cparam + (size_t)(r + 8) * DM + col) = make_float2(c[i][j][2] + bx, c[i][j][3] + by);
            }
        }
    }
}

// ---------------------------------------------------------------------------
// MMA flash attention, causal (unchanged from R10 passing version).
// ---------------------------------------------------------------------------
#define ASTR 72
#define ATILE (128 * ASTR)              // 9216 bf16
#define ATTN_SMEM (int)((2 * ATILE + 2 * 4 * ATILE) * sizeof(__nv_bfloat16))  // 184320 B

__device__ __forceinline__ void kv_load(uint32_t sbase, int tid, int kb, int buf, int hoff)
{
#pragma unroll
    for (int i = 0; i < 16; i++) {
        int id  = tid + 256 * i;
        int arr = id >> 10;
        int rem = id & 1023;
        int row = rem >> 3;
        int ch  = rem & 7;
        const __nv_bfloat16* src =
            ((arr == 0) ? g_kh : (arr == 1) ? g_kl : (arr == 2) ? g_vh : g_vl)
            + (size_t)(kb * 128 + row) * DM + hoff + ch * 8;
        uint32_t dst = sbase + (uint32_t)(18432 + buf * 36864 + arr * 9216 + row * ASTR + ch * 8) * 2;
        cp16(dst, src);
    }
}

__global__ __launch_bounds__(256, 1)
void attn_mma()
{
    extern __shared__ __nv_bfloat16 asm_sm[];
    const uint32_t sbase = smem_to_u32(asm_sm);

    const int qb   = gridDim.x - 1 - blockIdx.x;    // reversed: long CTAs first
    const int h    = blockIdx.y;
    const int hoff = h * HDIM;
    const int tid  = threadIdx.x;
    const int wid  = tid >> 5;
    const int lane = tid & 31;
    const int lr4  = lane >> 2;
    const int kq   = lane & 3;

    // Q load (cp.async)
#pragma unroll
    for (int i = 0; i < 8; i++) {
        int id  = tid + 256 * i;
        int arr = id >> 10;
        int rem = id & 1023;
        int row = rem >> 3;
        int ch  = rem & 7;
        const __nv_bfloat16* src = (arr ? g_ql : g_qh)
            + (size_t)(qb * 128 + row) * DM + hoff + ch * 8;
        uint32_t dst = sbase + (uint32_t)(arr * 9216 + row * ASTR + ch * 8) * 2;
        cp16(dst, src);
    }
    kv_load(sbase, tid, 0, 0, hoff);
    CP_COMMIT();

    const uint32_t qoff = (uint32_t)((wid * 16 + (lane & 7) + ((lane >> 3) & 1) * 8) * ASTR
                                     + ((lane >> 4) & 1) * 8);
    const uint32_t koff = (uint32_t)(((lane & 7) + ((lane >> 4) & 1) * 8) * ASTR
                                     + ((lane >> 3) & 1) * 8);
    const uint32_t voff = (uint32_t)(((lane & 7) + ((lane >> 3) & 1) * 8) * ASTR
                                     + ((lane >> 4) & 1) * 8);

    float o[8][4];
#pragma unroll
    for (int i = 0; i < 8; i++)
#pragma unroll
        for (int e = 0; e < 4; e++) o[i][e] = 0.f;
    float m_lo = -1e30f, m_hi = -1e30f, l_lo = 0.f, l_hi = 0.f;

    for (int kb = 0; kb <= qb; kb++) {
        const int buf = kb & 1;
        if (kb < qb) {
            kv_load(sbase, tid, kb + 1, buf ^ 1, hoff);
            CP_COMMIT();
            CP_WAIT1();
        } else {
            CP_WAIT0();
        }
        __syncthreads();

        const uint32_t Qh_b = sbase;
        const uint32_t Ql_b = sbase + 9216 * 2;
        const uint32_t Kh_b = sbase + (uint32_t)(18432 + buf * 36864) * 2;
        const uint32_t Kl_b = Kh_b + 9216 * 2;
        const uint32_t Vh_b = Kh_b + 2 * 9216 * 2;
        const uint32_t Vl_b = Kh_b + 3 * 9216 * 2;

        // ---- S = Q K^T ----
        float s[16][4];
#pragma unroll
        for (int j = 0; j < 16; j++)
#pragma unroll
            for (int e = 0; e < 4; e++) s[j][e] = 0.f;

#pragma unroll
        for (int ks = 0; ks < 4; ks++) {
            uint32_t ah[4], al[4];
            ldsm4(ah, Qh_b + (qoff + ks * 16) * 2);
            ldsm4(al, Ql_b + (qoff + ks * 16) * 2);
#pragma unroll
            for (int jp = 0; jp < 8; jp++) {
                uint32_t bh[4], bl[4];
                ldsm4(bh, Kh_b + (koff + jp * 16 * ASTR + ks * 16) * 2);
                ldsm4(bl, Kl_b + (koff + jp * 16 * ASTR + ks * 16) * 2);
                mma16816(s[2 * jp],     ah, bh);
                mma16816(s[2 * jp],     ah, bl);
                mma16816(s[2 * jp],     al, bh);
                mma16816(s[2 * jp + 1], ah, bh + 2);
                mma16816(s[2 * jp + 1], ah, bl + 2);
                mma16816(s[2 * jp + 1], al, bh + 2);
            }
        }

        // ---- causal mask (diag block only) ----
        if (kb == qb) {
            const int rl = wid * 16 + lr4;
#pragma unroll
            for (int j = 0; j < 16; j++) {
                int c0 = j * 8 + kq * 2;
                if (c0     > rl)     s[j][0] = -1e30f;
                if (c0 + 1 > rl)     s[j][1] = -1e30f;
                if (c0     > rl + 8) s[j][2] = -1e30f;
                if (c0 + 1 > rl + 8) s[j][3] = -1e30f;
            }
        }

        // ---- online softmax ----
        float bm_lo = -1e30f, bm_hi = -1e30f;
#pragma unroll
        for (int j = 0; j < 16; j++) {
            bm_lo = fmaxf(bm_lo, fmaxf(s[j][0], s[j][1]));
            bm_hi = fmaxf(bm_hi, fmaxf(s[j][2], s[j][3]));
        }
#pragma unroll
        for (int off = 1; off <= 2; off <<= 1) {
            bm_lo = fmaxf(bm_lo, __shfl_xor_sync(0xffffffffu, bm_lo, off));
            bm_hi = fmaxf(bm_hi, __shfl_xor_sync(0xffffffffu, bm_hi, off));
        }
        const float mn_lo = fmaxf(m_lo, bm_lo);
        const float mn_hi = fmaxf(m_hi, bm_hi);
        const float cor_lo = __expf(m_lo - mn_lo);
        const float cor_hi = __expf(m_hi - mn_hi);
        m_lo = mn_lo; m_hi = mn_hi;

        float sum_lo = 0.f, sum_hi = 0.f;
#pragma unroll
        for (int j = 0; j < 16; j++) {
            s[j][0] = __expf(s[j][0] - mn_lo);
            s[j][1] = __expf(s[j][1] - mn_lo);
            s[j][2] = __expf(s[j][2] - mn_hi);
            s[j][3] = __expf(s[j][3] - mn_hi);
            sum_lo += s[j][0] + s[j][1];
            sum_hi += s[j][2] + s[j][3];
        }
#pragma unroll
        for (int off = 1; off <= 2; off <<= 1) {
            sum_lo += __shfl_xor_sync(0xffffffffu, sum_lo, off);
            sum_hi += __shfl_xor_sync(0xffffffffu, sum_hi, off);
        }
        l_lo = l_lo * cor_lo + sum_lo;
        l_hi = l_hi * cor_hi + sum_hi;
#pragma unroll
        for (int j2 = 0; j2 < 8; j2++) {
            o[j2][0] *= cor_lo; o[j2][1] *= cor_lo;
            o[j2][2] *= cor_hi; o[j2][3] *= cor_hi;
        }

        // ---- O += P V ----
#pragma unroll
        for (int ks2 = 0; ks2 < 8; ks2++) {
            const int j0 = 2 * ks2, j1 = 2 * ks2 + 1;
            uint32_t ph[4], pl[4];
#pragma unroll
            for (int q4 = 0; q4 < 4; q4++) {
                const float p0 = (q4 < 2) ? s[j0][(q4 & 1) * 2]     : s[j1][(q4 & 1) * 2];
                const float p1 = (q4 < 2) ? s[j0][(q4 & 1) * 2 + 1] : s[j1][(q4 & 1) * 2 + 1];
                uint32_t hp = packbf(p0, p1);
                __nv_bfloat162 hb = *(__nv_bfloat162*)&hp;
                float r0 = p0 - __bfloat162float(hb.x);
                float r1 = p1 - __bfloat162float(hb.y);
                ph[q4] = hp;
                pl[q4] = packbf(r0, r1);
            }
#pragma unroll
            for (int jp2 = 0; jp2 < 4; jp2++) {
                uint32_t vh[4], vl[4];
                ldsm4t(vh, Vh_b + (voff + ks2 * 16 * ASTR + jp2 * 16) * 2);
                ldsm4t(vl, Vl_b + (voff + ks2 * 16 * ASTR + jp2 * 16) * 2);
                mma16816(o[2 * jp2],     ph, vh);
                mma16816(o[2 * jp2],     ph, vl);
                mma16816(o[2 * jp2],     pl, vh);
                mma16816(o[2 * jp2 + 1], ph, vh + 2);
                mma16816(o[2 * jp2 + 1], ph, vl + 2);
                mma16816(o[2 * jp2 + 1], pl, vh + 2);
            }
        }
        __syncthreads();
    }

    // ---- epilogue ----
    const float inv_lo = 1.0f / l_lo;
    const float inv_hi = 1.0f / l_hi;
    const int row_g = qb * 128 + wid * 16 + lr4;
#pragma unroll
    for (int j2 = 0; j2 < 8; j2++) {
        const int col = hoff + j2 * 8 + kq * 2;
        {
            float v0 = o[j2][0] * inv_lo, v1 = o[j2][1] * inv_lo;
            __nv_bfloat16 h0 = __float2bfloat16(v0);
            __nv_bfloat16 h1 = __float2bfloat16(v1);
            __nv_bfloat16 l0 = __float2bfloat16(v0 - __bfloat162float(h0));
            __nv_bfloat16 l1 = __float2bfloat16(v1 - __bfloat162float(h1));
            *(__nv_bfloat162*)&g_ch[(size_t)row_g * DM + col] = __halves2bfloat162(h0, h1);
            *(__nv_bfloat162*)&g_cl[(size_t)row_g * DM + col] = __halves2bfloat162(l0, l1);
        }
        {
            float v0 = o[j2][2] * inv_hi, v1 = o[j2][3] * inv_hi;
            __nv_bfloat16 h0 = __float2bfloat16(v0);
            __nv_bfloat16 h1 = __float2bfloat16(v1);
            __nv_bfloat16 l0 = __float2bfloat16(v0 - __bfloat162float(h0));
            __nv_bfloat16 l1 = __float2bfloat16(v1 - __bfloat162float(h1));
            *(__nv_bfloat162*)&g_ch[(size_t)(row_g + 8) * DM + col] = __halves2bfloat162(h0, h1);
            *(__nv_bfloat162*)&g_cl[(size_t)(row_g + 8) * DM + col] = __halves2bfloat162(l0, l1);
        }
    }
}

// ---------------------------------------------------------------------------
extern "C" void kernel_launch(void* const* d_in, const int* in_sizes, int n_in,
                              void* d_out, int out_size)
{
    const float* x  = (const float*)d_in[0];
    const float* Wq = (const float*)d_in[1];
    const float* Wk = (const float*)d_in[2];
    const float* Wv = (const float*)d_in[3];
    const float* Wo = (const float*)d_in[4];
    const float* bo = (const float*)d_in[5];
    float* out = (float*)d_out;

    cudaFuncSetAttribute(tc_gemm, cudaFuncAttributeMaxDynamicSharedMemorySize, TCG_SMEM);
    cudaFuncSetAttribute(attn_mma, cudaFuncAttributeMaxDynamicSharedMemorySize, ATTN_SMEM);

    const int n2x = SQ * DM / 2;
    const int n2w = DM * DM / 2;

    split_x<<<n2x / 256, 256>>>(x, n2x);
    split_w<<<dim3(n2w / 256, 4), 256>>>(Wq, Wk, Wv, Wo, n2w);

    tc_gemm<<<dim3(DM / 128, SQ / 128, 3), 256, TCG_SMEM>>>(0, 0, 0, nullptr, nullptr);  // QKV

    attn_mma<<<dim3(SQ / 128, NH), 256, ATTN_SMEM>>>();

    tc_gemm<<<dim3(DM / 128, SQ / 128, 1), 256, TCG_SMEM>>>(1, 3, 3, out, bo);           // out proj
}